// round 11
// baseline (speedup 1.0000x reference)
#include <cuda_runtime.h>
#include <cstdint>
#include <math.h>

#define Bq   4
#define Nq   4096
#define Cq   256
#define DKq  64
#define NROWS (Bq*Nq)          // 16384
#define NEG_BIG (-3.402823466e38f)

__device__ float g_Qf[NROWS*DKq];
__device__ float g_Kf[NROWS*DKq];
__device__ float g_Qh[NROWS*DKq];
__device__ float g_Kh[NROWS*DKq];
__device__ int   g_cand[NROWS*64];      // 64 candidate cols per row

__device__ __forceinline__ void fma2(unsigned long long &acc,
                                     unsigned long long a, unsigned long long b) {
    asm volatile("fma.rn.f32x2 %0, %1, %2, %0;" : "+l"(acc) : "l"(a), "l"(b));
}
__device__ __forceinline__ float tf32_rna(float v) {
    uint32_t b;
    asm("cvt.rna.tf32.f32 %0, %1;" : "=r"(b) : "f"(v));
    return __uint_as_float(b);
}
__device__ __forceinline__ uint32_t smem_u32(const void* p) {
    uint32_t a;
    asm("{ .reg .u64 t; cvta.to.shared.u64 t, %1; cvt.u32.u64 %0, t; }" : "=r"(a) : "l"(p));
    return a;
}
__device__ __forceinline__ void cpa16(uint32_t dst, const void* src) {
    asm volatile("cp.async.cg.shared.global [%0], [%1], 16;" :: "r"(dst), "l"(src));
}
// pack column id into low 12 mantissa bits of score
__device__ __forceinline__ float packf(float v, int col) {
    return __uint_as_float((__float_as_uint(v) & ~0xFFFu) | (unsigned)col);
}

// =====================================================================
// Kernel 1: projections (exact fp32) + tf32-hi emit + FULL output zero-fill
//   Fill rides proj's idle DRAM write bandwidth (268MB streaming stores,
//   interleaved with the FMA loop). Edge no longer touches the output.
// =====================================================================
#define XP 36

__global__ __launch_bounds__(256, 2) void proj_kernel(
        const float* __restrict__ x,
        const float* __restrict__ Wq,
        const float* __restrict__ Wk,
        float* __restrict__ out) {
    __shared__ float Xs[64*XP];
    __shared__ float Ws[128*XP];
    int t  = threadIdx.x;
    int rb = blockIdx.x;
    int b  = rb >> 6;
    int n0 = (rb & 63) << 6;
    int tx = t & 15, ty = t >> 4;
    int m0 = rb << 6;

    unsigned long long acc[4][8];
#pragma unroll
    for (int i = 0; i < 4; i++)
#pragma unroll
        for (int j = 0; j < 8; j++) acc[i][j] = 0ull;

    const float* xb = x + (size_t)(b*Nq + n0) * Cq;
    float4* out4 = (float4*)out;
    const float4 z4 = make_float4(0.f, 0.f, 0.f, 0.f);

    for (int c0 = 0; c0 < Cq; c0 += 32) {
        int it = c0 >> 5;                     // 0..7
#pragma unroll
        for (int s = 0; s < 2; s++) {
            int li = t + s*256;
            int r = li >> 3, cq = li & 7;
            float4 v = *(const float4*)(xb + (size_t)r*Cq + c0 + cq*4);
            *(float4*)(&Xs[r*XP + cq*4]) = v;
        }
#pragma unroll
        for (int s = 0; s < 16; s++) {
            int li  = t + s*256;
            int mat = li >> 11;
            int rem = li & 2047;
            int cc  = rem >> 6;
            int jj  = rem & 63;
            const float* W = mat ? Wk : Wq;
            Ws[(mat*64 + jj)*XP + cc] = W[(size_t)(c0+cc)*DKq + jj];
        }
        __syncthreads();

        // ---- zero-fill: 64 rows x 128 float4-cols of this iteration ----
#pragma unroll
        for (int s = 0; s < 32; s++) {
            int idx = t + s*256;              // 0..8191
            int r = idx >> 7, c = idx & 127;
            __stcs(&out4[(size_t)(m0 + r)*1024 + it*128 + c], z4);
        }

#pragma unroll
        for (int cc = 0; cc < 32; cc += 4) {
            ulonglong2 qv[4];
#pragma unroll
            for (int i = 0; i < 4; i++)
                qv[i] = *(const ulonglong2*)(&Xs[(ty + 16*i)*XP + cc]);
#pragma unroll
            for (int j = 0; j < 8; j++) {
                ulonglong2 wv = *(const ulonglong2*)(&Ws[(tx + 16*j)*XP + cc]);
#pragma unroll
                for (int i = 0; i < 4; i++) {
                    fma2(acc[i][j], qv[i].x, wv.x);
                    fma2(acc[i][j], qv[i].y, wv.y);
                }
            }
        }
        __syncthreads();
    }
#pragma unroll
    for (int i = 0; i < 4; i++) {
        size_t m = (size_t)rb*64 + ty + 16*i;
#pragma unroll
        for (int j = 0; j < 8; j++) {
            int col = tx + 16*j;
            union { unsigned long long u; float2 f; } cv; cv.u = acc[i][j];
            float v  = cv.f.x + cv.f.y;
            if (col < 64) {
                g_Qf[m*DKq + col] = v;
                g_Qh[m*DKq + col] = tf32_rna(v);
            } else {
                int k = col - 64;
                g_Kf[m*DKq + k] = v;
                g_Kh[m*DKq + k] = tf32_rna(v);
            }
        }
    }
}

// =====================================================================
// Kernel 2: approx tf32 GEMM + per-stream top-8 (packed), NO output writes
//   grid 256 CTAs: 64 query rows, ALL 4096 keys, 32 steps x 128 keys.
//   256 threads / 8 warps; warp = 16 rows (msub) x 64 keys (ksub).
//   A-fragments hoisted into registers (Q persistent): 128 LDS/warp/step.
//   2 CTAs/SM (87KB smem, ~100 regs, no spills).
// =====================================================================
#define QP     68
#define QPB    (QP*4)                   // 272 bytes
#define OFF_Q  0
#define QBYTES (64*QPB)                 // 17408
#define OFF_B0 QBYTES
#define BBYTES (128*QPB)                // 34816
#define OFF_B1 (OFF_B0 + BBYTES)
#define SMEM_EDGE (OFF_B1 + BBYTES)     // 87040

__device__ __forceinline__ void mma8(float c[4], uint32_t a0, uint32_t a1,
                                     uint32_t a2, uint32_t a3,
                                     uint32_t b0, uint32_t b1) {
    asm volatile(
        "mma.sync.aligned.m16n8k8.row.col.f32.tf32.tf32.f32 "
        "{%0,%1,%2,%3},{%4,%5,%6,%7},{%8,%9},{%0,%1,%2,%3};"
        : "+f"(c[0]), "+f"(c[1]), "+f"(c[2]), "+f"(c[3])
        : "r"(a0), "r"(a1), "r"(a2), "r"(a3), "r"(b0), "r"(b1));
}

__device__ __forceinline__ void ins8p(float* vals, float v, int col) {
    if (v > vals[7]) {
        float pv = packf(v, col);
#pragma unroll
        for (int q = 0; q < 8; q++) {
            if (pv > vals[q]) { float tv = vals[q]; vals[q] = pv; pv = tv; }
        }
    }
}

__global__ __launch_bounds__(256, 2)
void edge_kernel() {
    extern __shared__ __align__(16) char smem[];
    uint32_t sb = smem_u32(smem);
    const uint32_t* Qu = (const uint32_t*)(smem + OFF_Q);

    int tid = threadIdx.x;
    int wid = tid >> 5, lane = tid & 31;
    int g = lane >> 2, tg = lane & 3;
    int msub = wid >> 1, ksub = wid & 1;

    int m0    = blockIdx.x * 64;
    int batch = blockIdx.x >> 6;            // 64 CTAs per batch

    // ---- load Q-hi tile (64 x 64), own commit group ----
    const float* qsrc = g_Qh + (size_t)m0 * DKq;
#pragma unroll
    for (int i = 0; i < 4; i++) {
        int idx = tid + i*256;              // 0..1023
        int r = idx >> 4, c = idx & 15;
        cpa16(sb + OFF_Q + (uint32_t)(r*QPB + c*16), qsrc + (size_t)r*DKq + c*4);
    }
    asm volatile("cp.async.commit_group;");

    const float* gK = g_Kh + (size_t)batch * Nq * DKq;
    // prefetch step 0 (128 keys), second group
#pragma unroll
    for (int i = 0; i < 8; i++) {
        int idx = tid + i*256;              // 0..2047
        int r = idx >> 4, c = idx & 15;
        cpa16(sb + OFF_B0 + (uint32_t)(r*QPB + c*16), gK + (size_t)r*DKq + c*4);
    }
    asm volatile("cp.async.commit_group;");

    // Q ready (all groups except the newest B0 group)
    asm volatile("cp.async.wait_group 1;");
    __syncthreads();

    // ---- hoist A fragments (persistent across all steps): 32 regs ----
    uint32_t af[8][4];
    {
        int rr = msub*16 + g;
#pragma unroll
        for (int ks = 0; ks < 8; ks++) {
            int k0 = ks * 8;
            af[ks][0] = Qu[rr*QP + k0 + tg];
            af[ks][1] = Qu[(rr + 8)*QP + k0 + tg];
            af[ks][2] = Qu[rr*QP + k0 + 4 + tg];
            af[ks][3] = Qu[(rr + 8)*QP + k0 + 4 + tg];
        }
    }

    float vals[2][8];
#pragma unroll
    for (int l = 0; l < 2; l++)
#pragma unroll
        for (int q = 0; q < 8; q++) vals[l][q] = NEG_BIG;

    for (int step = 0; step < 32; step++) {
        const uint32_t* Bu = (const uint32_t*)(smem + ((step & 1) ? OFF_B1 : OFF_B0));
        if (step < 31) {
            uint32_t boff = (step & 1) ? OFF_B0 : OFF_B1;
            const float* src = gK + (size_t)(step + 1)*128*DKq;
#pragma unroll
            for (int i = 0; i < 8; i++) {
                int idx = tid + i*256;
                int r = idx >> 4, c = idx & 15;
                cpa16(sb + boff + (uint32_t)(r*QPB + c*16), src + (size_t)r*DKq + c*4);
            }
            asm volatile("cp.async.commit_group;");
            asm volatile("cp.async.wait_group 1;");
        } else {
            asm volatile("cp.async.wait_group 0;");
        }
        __syncthreads();

        // ---- warp tf32 GEMM: 16 rows x 64 keys, A from registers ----
        float c[8][4];
#pragma unroll
        for (int j = 0; j < 8; j++)
#pragma unroll
            for (int q = 0; q < 4; q++) c[j][q] = 0.f;

#pragma unroll
        for (int ks = 0; ks < 8; ks++) {
            int k0 = ks * 8;
#pragma unroll
            for (int j = 0; j < 8; j++) {
                int n = ksub*64 + j*8 + g;
                uint32_t b0 = Bu[n*QP + k0 + tg];
                uint32_t b1 = Bu[n*QP + k0 + 4 + tg];
                mma8(c[j], af[ks][0], af[ks][1], af[ks][2], af[ks][3], b0, b1);
            }
        }

        // ---- per-stream top-8 scan (packed) ----
#pragma unroll
        for (int j = 0; j < 8; j++) {
            int c0i = step*128 + ksub*64 + j*8 + 2*tg;
            ins8p(vals[0], c[j][0], c0i);
            ins8p(vals[0], c[j][1], c0i + 1);
            ins8p(vals[1], c[j][2], c0i);
            ins8p(vals[1], c[j][3], c0i + 1);
        }
        __syncthreads();
    }

    // ---- dump candidates: row streams (g, g+8), slot (ksub*4+tg)*8 ----
#pragma unroll
    for (int l = 0; l < 2; l++) {
        int row = m0 + msub*16 + l*8 + g;
        size_t base = (size_t)row*64 + (ksub*4 + tg)*8;
#pragma unroll
        for (int q = 0; q < 8; q++)
            g_cand[base + q] = (int)(__float_as_uint(vals[l][q]) & 0xFFFu);
    }
}

// =====================================================================
// Kernel 3: exact fp32 rescore (coalesced gather) + top-8 + softmax
// =====================================================================
__global__ __launch_bounds__(256) void rescore_kernel(float* __restrict__ out) {
    __shared__ float sd[8][64];
    int tid = threadIdx.x;
    int w = tid >> 5, lane = tid & 31;
    int row   = blockIdx.x*8 + w;
    int batch = row >> 12;
    int hl = lane & 15;

    const float* Kf = g_Kf + (size_t)batch * Nq * DKq;
    float4 qv = *(const float4*)(g_Qf + (size_t)row*DKq + hl*4);

    int c0 = g_cand[(size_t)row*64 + lane];
    int c1 = g_cand[(size_t)row*64 + 32 + lane];

#pragma unroll
    for (int it = 0; it < 32; it++) {
        int j = 2*it + (lane >> 4);
        int ca = __shfl_sync(0xFFFFFFFFu, c0, j & 31);
        int cb = __shfl_sync(0xFFFFFFFFu, c1, j & 31);
        int cnd = (it < 16) ? ca : cb;
        float4 kv = *(const float4*)(Kf + (size_t)cnd*DKq + hl*4);
        float p = qv.x*kv.x + qv.y*kv.y + qv.z*kv.z + qv.w*kv.w;
        p += __shfl_xor_sync(0xFFFFFFFFu, p, 1);
        p += __shfl_xor_sync(0xFFFFFFFFu, p, 2);
        p += __shfl_xor_sync(0xFFFFFFFFu, p, 4);
        p += __shfl_xor_sync(0xFFFFFFFFu, p, 8);
        if (hl == 0) sd[w][j] = p;
    }
    __syncwarp();

    float s0 = sd[w][lane];
    float s1 = sd[w][lane + 32];
    int   i0 = c0, i1 = c1;

    float bv[8]; int bi[8];
#pragma unroll
    for (int sel = 0; sel < 8; sel++) {
        float v; int ix;
        if (s0 > s1 || (s0 == s1 && i0 < i1)) { v = s0; ix = i0; }
        else                                  { v = s1; ix = i1; }
#pragma unroll
        for (int off = 16; off > 0; off >>= 1) {
            float vv = __shfl_xor_sync(0xFFFFFFFFu, v, off);
            int   ii = __shfl_xor_sync(0xFFFFFFFFu, ix, off);
            if (vv > v || (vv == v && ii < ix)) { v = vv; ix = ii; }
        }
        bv[sel] = v; bi[sel] = ix;
        if (i0 == ix) s0 = NEG_BIG;
        if (i1 == ix) s1 = NEG_BIG;
    }

    float mx = bv[0];
    float Z = 0.f, e[8];
#pragma unroll
    for (int q = 0; q < 8; q++) { e[q] = expf(0.125f*(bv[q] - mx)); Z += e[q]; }
    float inv = 1.0f / Z;
    if (lane < 8)
        out[(size_t)row*Nq + bi[lane]] = e[lane] * inv;
}

// =====================================================================
extern "C" void kernel_launch(void* const* d_in, const int* in_sizes, int n_in,
                              void* d_out, int out_size) {
    const float* x  = (const float*)d_in[0];
    const float* Wq = (const float*)d_in[1];
    const float* Wk = (const float*)d_in[2];
    float* out = (float*)d_out;

    cudaFuncSetAttribute(edge_kernel,
                         cudaFuncAttributeMaxDynamicSharedMemorySize, SMEM_EDGE);

    proj_kernel<<<NROWS/64, 256>>>(x, Wq, Wk, out);
    edge_kernel<<<NROWS/64, 256, SMEM_EDGE>>>();      // 256 CTAs
    rescore_kernel<<<NROWS/8, 256>>>(out);
}

// round 12
// speedup vs baseline: 1.0767x; 1.0767x over previous
#include <cuda_runtime.h>
#include <cuda_fp16.h>
#include <cstdint>
#include <math.h>

#define Bq   4
#define Nq   4096
#define Cq   256
#define DKq  64
#define NROWS (Bq*Nq)          // 16384
#define NEG_BIG (-3.402823466e38f)

__device__ float  g_Qf[NROWS*DKq];
__device__ float  g_Kf[NROWS*DKq];
__device__ __half g_Qh[NROWS*DKq];
__device__ __half g_Kh[NROWS*DKq];
__device__ int    g_cand[NROWS*64];     // 64 candidate cols per row

__device__ __forceinline__ void fma2(unsigned long long &acc,
                                     unsigned long long a, unsigned long long b) {
    asm volatile("fma.rn.f32x2 %0, %1, %2, %0;" : "+l"(acc) : "l"(a), "l"(b));
}
__device__ __forceinline__ uint32_t smem_u32(const void* p) {
    uint32_t a;
    asm("{ .reg .u64 t; cvta.to.shared.u64 t, %1; cvt.u32.u64 %0, t; }" : "=r"(a) : "l"(p));
    return a;
}
__device__ __forceinline__ void cpa16(uint32_t dst, const void* src) {
    asm volatile("cp.async.cg.shared.global [%0], [%1], 16;" :: "r"(dst), "l"(src));
}
// pack column id into low 12 mantissa bits of score
__device__ __forceinline__ float packf(float v, int col) {
    return __uint_as_float((__float_as_uint(v) & ~0xFFFu) | (unsigned)col);
}

// =====================================================================
// Kernel 1: projections (exact fp32) + fp16 emit + FULL output zero-fill
// =====================================================================
#define XP 36

__global__ __launch_bounds__(256, 2) void proj_kernel(
        const float* __restrict__ x,
        const float* __restrict__ Wq,
        const float* __restrict__ Wk,
        float* __restrict__ out) {
    __shared__ float Xs[64*XP];
    __shared__ float Ws[128*XP];
    int t  = threadIdx.x;
    int rb = blockIdx.x;
    int b  = rb >> 6;
    int n0 = (rb & 63) << 6;
    int tx = t & 15, ty = t >> 4;
    int m0 = rb << 6;

    unsigned long long acc[4][8];
#pragma unroll
    for (int i = 0; i < 4; i++)
#pragma unroll
        for (int j = 0; j < 8; j++) acc[i][j] = 0ull;

    const float* xb = x + (size_t)(b*Nq + n0) * Cq;
    float4* out4 = (float4*)out;
    const float4 z4 = make_float4(0.f, 0.f, 0.f, 0.f);

    for (int c0 = 0; c0 < Cq; c0 += 32) {
        int it = c0 >> 5;
#pragma unroll
        for (int s = 0; s < 2; s++) {
            int li = t + s*256;
            int r = li >> 3, cq = li & 7;
            float4 v = *(const float4*)(xb + (size_t)r*Cq + c0 + cq*4);
            *(float4*)(&Xs[r*XP + cq*4]) = v;
        }
#pragma unroll
        for (int s = 0; s < 16; s++) {
            int li  = t + s*256;
            int mat = li >> 11;
            int rem = li & 2047;
            int cc  = rem >> 6;
            int jj  = rem & 63;
            const float* W = mat ? Wk : Wq;
            Ws[(mat*64 + jj)*XP + cc] = W[(size_t)(c0+cc)*DKq + jj];
        }
        __syncthreads();

        // ---- zero-fill: 64 rows x 128 float4-cols of this iteration ----
#pragma unroll
        for (int s = 0; s < 32; s++) {
            int idx = t + s*256;
            int r = idx >> 7, c = idx & 127;
            __stcs(&out4[(size_t)(m0 + r)*1024 + it*128 + c], z4);
        }

#pragma unroll
        for (int cc = 0; cc < 32; cc += 4) {
            ulonglong2 qv[4];
#pragma unroll
            for (int i = 0; i < 4; i++)
                qv[i] = *(const ulonglong2*)(&Xs[(ty + 16*i)*XP + cc]);
#pragma unroll
            for (int j = 0; j < 8; j++) {
                ulonglong2 wv = *(const ulonglong2*)(&Ws[(tx + 16*j)*XP + cc]);
#pragma unroll
                for (int i = 0; i < 4; i++) {
                    fma2(acc[i][j], qv[i].x, wv.x);
                    fma2(acc[i][j], qv[i].y, wv.y);
                }
            }
        }
        __syncthreads();
    }
#pragma unroll
    for (int i = 0; i < 4; i++) {
        size_t m = (size_t)rb*64 + ty + 16*i;
#pragma unroll
        for (int j = 0; j < 8; j++) {
            int col = tx + 16*j;
            union { unsigned long long u; float2 f; } cv; cv.u = acc[i][j];
            float v  = cv.f.x + cv.f.y;
            if (col < 64) {
                g_Qf[m*DKq + col] = v;
                g_Qh[m*DKq + col] = __float2half(v);
            } else {
                int k = col - 64;
                g_Kf[m*DKq + k] = v;
                g_Kh[m*DKq + k] = __float2half(v);
            }
        }
    }
}

// =====================================================================
// Kernel 2: approx fp16 GEMM (m16n8k16) + per-stream top-8 (packed)
//   grid 256 CTAs: 64 query rows, ALL 4096 keys, 32 steps x 128 keys.
//   256 threads / 8 warps; warp = 16 rows (msub) x 64 keys (ksub).
//   A-fragments hoisted (16 regs). 3 CTAs/SM target (46KB smem, 84 regs).
//   Pitch 144B: bank = (4g+tg) mod 32 -> conflict-free fragment LDS.
// =====================================================================
#define PH     72                       // pitch in halves
#define PHB    144                      // pitch bytes
#define PW     36                       // pitch in 32-bit words
#define OFF_Q  0
#define QBYTES (64*PHB)                 // 9216
#define OFF_B0 QBYTES
#define BBYTES (128*PHB)                // 18432
#define OFF_B1 (OFF_B0 + BBYTES)
#define SMEM_EDGE (OFF_B1 + BBYTES)     // 46080

__device__ __forceinline__ void mma16(float c[4], uint32_t a0, uint32_t a1,
                                      uint32_t a2, uint32_t a3,
                                      uint32_t b0, uint32_t b1) {
    asm volatile(
        "mma.sync.aligned.m16n8k16.row.col.f32.f16.f16.f32 "
        "{%0,%1,%2,%3},{%4,%5,%6,%7},{%8,%9},{%0,%1,%2,%3};"
        : "+f"(c[0]), "+f"(c[1]), "+f"(c[2]), "+f"(c[3])
        : "r"(a0), "r"(a1), "r"(a2), "r"(a3), "r"(b0), "r"(b1));
}

__device__ __forceinline__ void ins8p(float* vals, float v, int col) {
    if (v > vals[7]) {
        float pv = packf(v, col);
#pragma unroll
        for (int q = 0; q < 8; q++) {
            if (pv > vals[q]) { float tv = vals[q]; vals[q] = pv; pv = tv; }
        }
    }
}

__global__ __launch_bounds__(256, 3)
void edge_kernel() {
    extern __shared__ __align__(16) char smem[];
    uint32_t sb = smem_u32(smem);
    const uint32_t* Qu = (const uint32_t*)(smem + OFF_Q);

    int tid = threadIdx.x;
    int wid = tid >> 5, lane = tid & 31;
    int g = lane >> 2, tg = lane & 3;
    int msub = wid >> 1, ksub = wid & 1;

    int m0    = blockIdx.x * 64;
    int batch = blockIdx.x >> 6;            // 64 CTAs per batch

    // ---- load Q-half tile (64 x 64): 2 chunks/thread ----
    const __half* qsrc = g_Qh + (size_t)m0 * DKq;
#pragma unroll
    for (int i = 0; i < 2; i++) {
        int idx = tid + i*256;              // 0..511
        int r = idx >> 3, c = idx & 7;
        cpa16(sb + OFF_Q + (uint32_t)(r*PHB + c*16), qsrc + (size_t)r*DKq + c*8);
    }
    asm volatile("cp.async.commit_group;");

    const __half* gK = g_Kh + (size_t)batch * Nq * DKq;
    // prefetch step 0 (128 keys): 4 chunks/thread
#pragma unroll
    for (int i = 0; i < 4; i++) {
        int idx = tid + i*256;              // 0..1023
        int r = idx >> 3, c = idx & 7;
        cpa16(sb + OFF_B0 + (uint32_t)(r*PHB + c*16), gK + (size_t)r*DKq + c*8);
    }
    asm volatile("cp.async.commit_group;");

    asm volatile("cp.async.wait_group 1;"); // Q ready
    __syncthreads();

    // ---- hoist A fragments: 4 k-steps x 4 regs = 16 regs ----
    uint32_t af[4][4];
    {
        int rr = msub*16 + g;
#pragma unroll
        for (int ks = 0; ks < 4; ks++) {
            af[ks][0] = Qu[rr*PW + ks*8 + tg];
            af[ks][1] = Qu[(rr + 8)*PW + ks*8 + tg];
            af[ks][2] = Qu[rr*PW + ks*8 + 4 + tg];
            af[ks][3] = Qu[(rr + 8)*PW + ks*8 + 4 + tg];
        }
    }

    float vals[2][8];
#pragma unroll
    for (int l = 0; l < 2; l++)
#pragma unroll
        for (int q = 0; q < 8; q++) vals[l][q] = NEG_BIG;

    for (int step = 0; step < 32; step++) {
        const uint32_t* Bu = (const uint32_t*)(smem + ((step & 1) ? OFF_B1 : OFF_B0));
        if (step < 31) {
            uint32_t boff = (step & 1) ? OFF_B0 : OFF_B1;
            const __half* src = gK + (size_t)(step + 1)*128*DKq;
#pragma unroll
            for (int i = 0; i < 4; i++) {
                int idx = tid + i*256;
                int r = idx >> 3, c = idx & 7;
                cpa16(sb + boff + (uint32_t)(r*PHB + c*16), src + (size_t)r*DKq + c*8);
            }
            asm volatile("cp.async.commit_group;");
            asm volatile("cp.async.wait_group 1;");
        } else {
            asm volatile("cp.async.wait_group 0;");
        }
        __syncthreads();

        // ---- warp fp16 GEMM: 16 rows x 64 keys, K=64 in 4 k16 steps ----
        float c[8][4];
#pragma unroll
        for (int j = 0; j < 8; j++)
#pragma unroll
            for (int q = 0; q < 4; q++) c[j][q] = 0.f;

#pragma unroll
        for (int ks = 0; ks < 4; ks++) {
#pragma unroll
            for (int j = 0; j < 8; j++) {
                int n = ksub*64 + j*8 + g;
                uint32_t b0 = Bu[n*PW + ks*8 + tg];
                uint32_t b1 = Bu[n*PW + ks*8 + 4 + tg];
                mma16(c[j], af[ks][0], af[ks][1], af[ks][2], af[ks][3], b0, b1);
            }
        }

        // ---- per-stream top-8 scan (packed) ----
#pragma unroll
        for (int j = 0; j < 8; j++) {
            int c0i = step*128 + ksub*64 + j*8 + 2*tg;
            ins8p(vals[0], c[j][0], c0i);
            ins8p(vals[0], c[j][1], c0i + 1);
            ins8p(vals[1], c[j][2], c0i);
            ins8p(vals[1], c[j][3], c0i + 1);
        }
        __syncthreads();
    }

    // ---- dump candidates: row streams (g, g+8), slot (ksub*4+tg)*8 ----
#pragma unroll
    for (int l = 0; l < 2; l++) {
        int row = m0 + msub*16 + l*8 + g;
        size_t base = (size_t)row*64 + (ksub*4 + tg)*8;
#pragma unroll
        for (int q = 0; q < 8; q++)
            g_cand[base + q] = (int)(__float_as_uint(vals[l][q]) & 0xFFFu);
    }
}

// =====================================================================
// Kernel 3: exact fp32 rescore (coalesced gather) + top-8 + softmax
// =====================================================================
__global__ __launch_bounds__(256) void rescore_kernel(float* __restrict__ out) {
    __shared__ float sd[8][64];
    int tid = threadIdx.x;
    int w = tid >> 5, lane = tid & 31;
    int row   = blockIdx.x*8 + w;
    int batch = row >> 12;
    int hl = lane & 15;

    const float* Kf = g_Kf + (size_t)batch * Nq * DKq;
    float4 qv = *(const float4*)(g_Qf + (size_t)row*DKq + hl*4);

    int c0 = g_cand[(size_t)row*64 + lane];
    int c1 = g_cand[(size_t)row*64 + 32 + lane];

#pragma unroll
    for (int it = 0; it < 32; it++) {
        int j = 2*it + (lane >> 4);
        int ca = __shfl_sync(0xFFFFFFFFu, c0, j & 31);
        int cb = __shfl_sync(0xFFFFFFFFu, c1, j & 31);
        int cnd = (it < 16) ? ca : cb;
        float4 kv = *(const float4*)(Kf + (size_t)cnd*DKq + hl*4);
        float p = qv.x*kv.x + qv.y*kv.y + qv.z*kv.z + qv.w*kv.w;
        p += __shfl_xor_sync(0xFFFFFFFFu, p, 1);
        p += __shfl_xor_sync(0xFFFFFFFFu, p, 2);
        p += __shfl_xor_sync(0xFFFFFFFFu, p, 4);
        p += __shfl_xor_sync(0xFFFFFFFFu, p, 8);
        if (hl == 0) sd[w][j] = p;
    }
    __syncwarp();

    float s0 = sd[w][lane];
    float s1 = sd[w][lane + 32];
    int   i0 = c0, i1 = c1;

    float bv[8]; int bi[8];
#pragma unroll
    for (int sel = 0; sel < 8; sel++) {
        float v; int ix;
        if (s0 > s1 || (s0 == s1 && i0 < i1)) { v = s0; ix = i0; }
        else                                  { v = s1; ix = i1; }
#pragma unroll
        for (int off = 16; off > 0; off >>= 1) {
            float vv = __shfl_xor_sync(0xFFFFFFFFu, v, off);
            int   ii = __shfl_xor_sync(0xFFFFFFFFu, ix, off);
            if (vv > v || (vv == v && ii < ix)) { v = vv; ix = ii; }
        }
        bv[sel] = v; bi[sel] = ix;
        if (i0 == ix) s0 = NEG_BIG;
        if (i1 == ix) s1 = NEG_BIG;
    }

    float mx = bv[0];
    float Z = 0.f, e[8];
#pragma unroll
    for (int q = 0; q < 8; q++) { e[q] = expf(0.125f*(bv[q] - mx)); Z += e[q]; }
    float inv = 1.0f / Z;
    if (lane < 8)
        out[(size_t)row*Nq + bi[lane]] = e[lane] * inv;
}

// =====================================================================
extern "C" void kernel_launch(void* const* d_in, const int* in_sizes, int n_in,
                              void* d_out, int out_size) {
    const float* x  = (const float*)d_in[0];
    const float* Wq = (const float*)d_in[1];
    const float* Wk = (const float*)d_in[2];
    float* out = (float*)d_out;

    cudaFuncSetAttribute(edge_kernel,
                         cudaFuncAttributeMaxDynamicSharedMemorySize, SMEM_EDGE);

    proj_kernel<<<NROWS/64, 256>>>(x, Wq, Wk, out);
    edge_kernel<<<NROWS/64, 256, SMEM_EDGE>>>();      // 256 CTAs
    rescore_kernel<<<NROWS/8, 256>>>(out);
}

// round 13
// speedup vs baseline: 1.1685x; 1.0853x over previous
#include <cuda_runtime.h>
#include <cuda_fp16.h>
#include <cstdint>
#include <math.h>

#define Bq   4
#define Nq   4096
#define Cq   256
#define DKq  64
#define NROWS (Bq*Nq)          // 16384
#define NEG_BIG (-3.402823466e38f)

__device__ float  g_Qf[NROWS*DKq];
__device__ float  g_Kf[NROWS*DKq];
__device__ __half g_Qh[NROWS*DKq];
__device__ __half g_Kh[NROWS*DKq];
__device__ int    g_cand[NROWS*64];     // 64 candidate cols per row

__device__ __forceinline__ void fma2(unsigned long long &acc,
                                     unsigned long long a, unsigned long long b) {
    asm volatile("fma.rn.f32x2 %0, %1, %2, %0;" : "+l"(acc) : "l"(a), "l"(b));
}
__device__ __forceinline__ uint32_t smem_u32(const void* p) {
    uint32_t a;
    asm("{ .reg .u64 t; cvta.to.shared.u64 t, %1; cvt.u32.u64 %0, t; }" : "=r"(a) : "l"(p));
    return a;
}
__device__ __forceinline__ void cpa16(uint32_t dst, const void* src) {
    asm volatile("cp.async.cg.shared.global [%0], [%1], 16;" :: "r"(dst), "l"(src));
}
// pack column id into low 12 mantissa bits of score
__device__ __forceinline__ float packf(float v, int col) {
    return __uint_as_float((__float_as_uint(v) & ~0xFFFu) | (unsigned)col);
}

// =====================================================================
// Kernel 1: projections (exact fp32) + fp16 emit — fill-free (~40us)
// =====================================================================
#define XP 36

__global__ __launch_bounds__(256, 2) void proj_kernel(
        const float* __restrict__ x,
        const float* __restrict__ Wq,
        const float* __restrict__ Wk) {
    __shared__ float Xs[64*XP];
    __shared__ float Ws[128*XP];
    int t  = threadIdx.x;
    int rb = blockIdx.x;
    int b  = rb >> 6;
    int n0 = (rb & 63) << 6;
    int tx = t & 15, ty = t >> 4;

    unsigned long long acc[4][8];
#pragma unroll
    for (int i = 0; i < 4; i++)
#pragma unroll
        for (int j = 0; j < 8; j++) acc[i][j] = 0ull;

    const float* xb = x + (size_t)(b*Nq + n0) * Cq;

    for (int c0 = 0; c0 < Cq; c0 += 32) {
#pragma unroll
        for (int s = 0; s < 2; s++) {
            int li = t + s*256;
            int r = li >> 3, cq = li & 7;
            float4 v = *(const float4*)(xb + (size_t)r*Cq + c0 + cq*4);
            *(float4*)(&Xs[r*XP + cq*4]) = v;
        }
#pragma unroll
        for (int s = 0; s < 16; s++) {
            int li  = t + s*256;
            int mat = li >> 11;
            int rem = li & 2047;
            int cc  = rem >> 6;
            int jj  = rem & 63;
            const float* W = mat ? Wk : Wq;
            Ws[(mat*64 + jj)*XP + cc] = W[(size_t)(c0+cc)*DKq + jj];
        }
        __syncthreads();
#pragma unroll
        for (int cc = 0; cc < 32; cc += 4) {
            ulonglong2 qv[4];
#pragma unroll
            for (int i = 0; i < 4; i++)
                qv[i] = *(const ulonglong2*)(&Xs[(ty + 16*i)*XP + cc]);
#pragma unroll
            for (int j = 0; j < 8; j++) {
                ulonglong2 wv = *(const ulonglong2*)(&Ws[(tx + 16*j)*XP + cc]);
#pragma unroll
                for (int i = 0; i < 4; i++) {
                    fma2(acc[i][j], qv[i].x, wv.x);
                    fma2(acc[i][j], qv[i].y, wv.y);
                }
            }
        }
        __syncthreads();
    }
#pragma unroll
    for (int i = 0; i < 4; i++) {
        size_t m = (size_t)rb*64 + ty + 16*i;
#pragma unroll
        for (int j = 0; j < 8; j++) {
            int col = tx + 16*j;
            union { unsigned long long u; float2 f; } cv; cv.u = acc[i][j];
            float v  = cv.f.x + cv.f.y;
            if (col < 64) {
                g_Qf[m*DKq + col] = v;
                g_Qh[m*DKq + col] = __float2half(v);
            } else {
                int k = col - 64;
                g_Kf[m*DKq + k] = v;
                g_Kh[m*DKq + k] = __float2half(v);
            }
        }
    }
}

// =====================================================================
// Kernel 2: fp16 approx GEMM + interleaved zero-fill + per-stream top-8
//   grid 512: (64-row block) x (2048-key half). 256 threads / 8 warps.
//   warp = 16 rows (msub) x 64 keys (ksub); 16 steps x 128 keys.
//   j-loop split in halves (16 accum regs) -> fits 84-reg clamp, 3 CTAs/SM.
//   Epilogue: smem merge of ksub pairs (packed floats) -> 32 cand/half.
// =====================================================================
#define PH     72                       // pitch in halves
#define PHB    144                      // pitch bytes
#define PW     36                       // pitch in 32-bit words
#define OFF_Q  0
#define QBYTES (64*PHB)                 // 9216
#define OFF_B0 QBYTES
#define BBYTES (128*PHB)                // 18432
#define OFF_B1 (OFF_B0 + BBYTES)
#define SMEM_EDGE (OFF_B1 + BBYTES)     // 46080

__device__ __forceinline__ void mma16(float c[4], uint32_t a0, uint32_t a1,
                                      uint32_t a2, uint32_t a3,
                                      uint32_t b0, uint32_t b1) {
    asm volatile(
        "mma.sync.aligned.m16n8k16.row.col.f32.f16.f16.f32 "
        "{%0,%1,%2,%3},{%4,%5,%6,%7},{%8,%9},{%0,%1,%2,%3};"
        : "+f"(c[0]), "+f"(c[1]), "+f"(c[2]), "+f"(c[3])
        : "r"(a0), "r"(a1), "r"(a2), "r"(a3), "r"(b0), "r"(b1));
}

__device__ __forceinline__ void ins8p(float* vals, float v, int col) {
    if (v > vals[7]) {
        float pv = packf(v, col);
#pragma unroll
        for (int q = 0; q < 8; q++) {
            if (pv > vals[q]) { float tv = vals[q]; vals[q] = pv; pv = tv; }
        }
    }
}

__global__ __launch_bounds__(256, 3)
void edge_kernel(float* __restrict__ out) {
    extern __shared__ __align__(16) char smem[];
    uint32_t sb = smem_u32(smem);
    const uint32_t* Qu = (const uint32_t*)(smem + OFF_Q);

    int tid = threadIdx.x;
    int wid = tid >> 5, lane = tid & 31;
    int g = lane >> 2, tg = lane & 3;
    int msub = wid >> 1, ksub = wid & 1;

    int bid  = blockIdx.x;
    int rb   = bid >> 1;
    int half = bid & 1;
    int m0    = rb * 64;
    int batch = rb >> 6;                    // 64 row-blocks per batch
    int key0  = half * 2048;

    // ---- load Q-half tile (64 x 64) ----
    const __half* qsrc = g_Qh + (size_t)m0 * DKq;
#pragma unroll
    for (int i = 0; i < 2; i++) {
        int idx = tid + i*256;              // 0..511
        int r = idx >> 3, c = idx & 7;
        cpa16(sb + OFF_Q + (uint32_t)(r*PHB + c*16), qsrc + (size_t)r*DKq + c*8);
    }
    asm volatile("cp.async.commit_group;");

    const __half* gK = g_Kh + (size_t)(batch*Nq + key0) * DKq;
    // prefetch step 0 (128 keys)
#pragma unroll
    for (int i = 0; i < 4; i++) {
        int idx = tid + i*256;              // 0..1023
        int r = idx >> 3, c = idx & 7;
        cpa16(sb + OFF_B0 + (uint32_t)(r*PHB + c*16), gK + (size_t)r*DKq + c*8);
    }
    asm volatile("cp.async.commit_group;");

    asm volatile("cp.async.wait_group 1;"); // Q ready
    __syncthreads();

    // ---- hoist A fragments: 16 regs ----
    uint32_t af[4][4];
    {
        int rr = msub*16 + g;
#pragma unroll
        for (int ks = 0; ks < 4; ks++) {
            af[ks][0] = Qu[rr*PW + ks*8 + tg];
            af[ks][1] = Qu[(rr + 8)*PW + ks*8 + tg];
            af[ks][2] = Qu[rr*PW + ks*8 + 4 + tg];
            af[ks][3] = Qu[(rr + 8)*PW + ks*8 + 4 + tg];
        }
    }

    float vals[2][8];
#pragma unroll
    for (int l = 0; l < 2; l++)
#pragma unroll
        for (int q = 0; q < 8; q++) vals[l][q] = NEG_BIG;

    float4* out4 = (float4*)out;
    const float4 z4 = make_float4(0.f, 0.f, 0.f, 0.f);

    for (int step = 0; step < 16; step++) {
        const uint32_t* Bu = (const uint32_t*)(smem + ((step & 1) ? OFF_B1 : OFF_B0));
        if (step < 15) {
            uint32_t boff = (step & 1) ? OFF_B0 : OFF_B1;
            const __half* src = gK + (size_t)(step + 1)*128*DKq;
#pragma unroll
            for (int i = 0; i < 4; i++) {
                int idx = tid + i*256;
                int r = idx >> 3, c = idx & 7;
                cpa16(sb + boff + (uint32_t)(r*PHB + c*16), src + (size_t)r*DKq + c*8);
            }
            asm volatile("cp.async.commit_group;");
            asm volatile("cp.async.wait_group 1;");
        } else {
            asm volatile("cp.async.wait_group 0;");
        }
        __syncthreads();

        // ---- interleaved zero-fill: 64 rows x 32 float4-cols this step ----
#pragma unroll
        for (int s = 0; s < 8; s++) {
            int idx = tid + s*256;          // 0..2047
            int r = idx >> 5, c = idx & 31;
            __stcs(&out4[(size_t)(m0 + r)*1024 + half*512 + step*32 + c], z4);
        }

        // ---- fp16 GEMM + scan, split into two j-halves (16 accum regs) ----
#pragma unroll
        for (int h = 0; h < 2; h++) {
            float c[4][4];
#pragma unroll
            for (int j = 0; j < 4; j++)
#pragma unroll
                for (int q = 0; q < 4; q++) c[j][q] = 0.f;

#pragma unroll
            for (int ks = 0; ks < 4; ks++) {
#pragma unroll
                for (int j = 0; j < 4; j++) {
                    int n = ksub*64 + (h*4 + j)*8 + g;
                    uint32_t b0 = Bu[n*PW + ks*8 + tg];
                    uint32_t b1 = Bu[n*PW + ks*8 + 4 + tg];
                    mma16(c[j], af[ks][0], af[ks][1], af[ks][2], af[ks][3], b0, b1);
                }
            }
#pragma unroll
            for (int j = 0; j < 4; j++) {
                int c0i = key0 + step*128 + ksub*64 + (h*4 + j)*8 + 2*tg;
                ins8p(vals[0], c[j][0], c0i);
                ins8p(vals[0], c[j][1], c0i + 1);
                ins8p(vals[1], c[j][2], c0i);
                ins8p(vals[1], c[j][3], c0i + 1);
            }
        }
        __syncthreads();
    }

    // ---- merge ksub pairs via smem (B region dead): packed floats only ----
    float* MV = (float*)(smem + OFF_B0);    // [64*4][17] = 17408B
#pragma unroll
    for (int l = 0; l < 2; l++) {
        int rowLocal = msub*16 + l*8 + g;
#pragma unroll
        for (int q = 0; q < 8; q++)
            MV[(rowLocal*4 + tg)*17 + ksub*8 + q] = vals[l][q];
    }
    __syncthreads();
    {
        int rowLocal = tid >> 2, t4 = tid & 3;      // 256 tasks
        const float* A = &MV[(rowLocal*4 + t4)*17];
        size_t base = (size_t)(m0 + rowLocal)*64 + half*32 + t4*8;
        int pa = 0, pb = 8;
#pragma unroll
        for (int q = 0; q < 8; q++) {
            bool ta = (pa < 8) && (pb >= 16 || A[pa] >= A[pb]);
            int src = ta ? pa : pb;
            g_cand[base + q] = (int)(__float_as_uint(A[src]) & 0xFFFu);
            if (ta) pa++; else pb++;
        }
    }
}

// =====================================================================
// Kernel 3: exact fp32 rescore (coalesced gather) + top-8 + softmax
// =====================================================================
__global__ __launch_bounds__(256) void rescore_kernel(float* __restrict__ out) {
    __shared__ float sd[8][64];
    int tid = threadIdx.x;
    int w = tid >> 5, lane = tid & 31;
    int row   = blockIdx.x*8 + w;
    int batch = row >> 12;
    int hl = lane & 15;

    const float* Kf = g_Kf + (size_t)batch * Nq * DKq;
    float4 qv = *(const float4*)(g_Qf + (size_t)row*DKq + hl*4);

    int c0 = g_cand[(size_t)row*64 + lane];
    int c1 = g_cand[(size_t)row*64 + 32 + lane];

#pragma unroll
    for (int it = 0; it < 32; it++) {
        int j = 2*it + (lane >> 4);
        int ca = __shfl_sync(0xFFFFFFFFu, c0, j & 31);
        int cb = __shfl_sync(0xFFFFFFFFu, c1, j & 31);
        int cnd = (it < 16) ? ca : cb;
        float4 kv = *(const float4*)(Kf + (size_t)cnd*DKq + hl*4);
        float p = qv.x*kv.x + qv.y*kv.y + qv.z*kv.z + qv.w*kv.w;
        p += __shfl_xor_sync(0xFFFFFFFFu, p, 1);
        p += __shfl_xor_sync(0xFFFFFFFFu, p, 2);
        p += __shfl_xor_sync(0xFFFFFFFFu, p, 4);
        p += __shfl_xor_sync(0xFFFFFFFFu, p, 8);
        if (hl == 0) sd[w][j] = p;
    }
    __syncwarp();

    float s0 = sd[w][lane];
    float s1 = sd[w][lane + 32];
    int   i0 = c0, i1 = c1;

    float bv[8]; int bi[8];
#pragma unroll
    for (int sel = 0; sel < 8; sel++) {
        float v; int ix;
        if (s0 > s1 || (s0 == s1 && i0 < i1)) { v = s0; ix = i0; }
        else                                  { v = s1; ix = i1; }
#pragma unroll
        for (int off = 16; off > 0; off >>= 1) {
            float vv = __shfl_xor_sync(0xFFFFFFFFu, v, off);
            int   ii = __shfl_xor_sync(0xFFFFFFFFu, ix, off);
            if (vv > v || (vv == v && ii < ix)) { v = vv; ix = ii; }
        }
        bv[sel] = v; bi[sel] = ix;
        if (i0 == ix) s0 = NEG_BIG;
        if (i1 == ix) s1 = NEG_BIG;
    }

    float mx = bv[0];
    float Z = 0.f, e[8];
#pragma unroll
    for (int q = 0; q < 8; q++) { e[q] = expf(0.125f*(bv[q] - mx)); Z += e[q]; }
    float inv = 1.0f / Z;
    if (lane < 8)
        out[(size_t)row*Nq + bi[lane]] = e[lane] * inv;
}

// =====================================================================
extern "C" void kernel_launch(void* const* d_in, const int* in_sizes, int n_in,
                              void* d_out, int out_size) {
    const float* x  = (const float*)d_in[0];
    const float* Wq = (const float*)d_in[1];
    const float* Wk = (const float*)d_in[2];
    float* out = (float*)d_out;

    cudaFuncSetAttribute(edge_kernel,
                         cudaFuncAttributeMaxDynamicSharedMemorySize, SMEM_EDGE);

    proj_kernel<<<NROWS/64, 256>>>(x, Wq, Wk);
    edge_kernel<<<NROWS/32, 256, SMEM_EDGE>>>(out);   // 512 CTAs
    rescore_kernel<<<NROWS/8, 256>>>(out);
}

// round 14
// speedup vs baseline: 1.2085x; 1.0342x over previous
#include <cuda_runtime.h>
#include <cuda_fp16.h>
#include <cstdint>
#include <math.h>

#define Bq   4
#define Nq   4096
#define Cq   256
#define DKq  64
#define NROWS (Bq*Nq)          // 16384
#define NEG_BIG (-3.402823466e38f)

__device__ float  g_Qf[NROWS*DKq];
__device__ float  g_Kf[NROWS*DKq];
__device__ __half g_Qh[NROWS*DKq];
__device__ __half g_Kh[NROWS*DKq];
__device__ int    g_cand[NROWS*16];     // 16 candidate cols per row

__device__ __forceinline__ void fma2(unsigned long long &acc,
                                     unsigned long long a, unsigned long long b) {
    asm volatile("fma.rn.f32x2 %0, %1, %2, %0;" : "+l"(acc) : "l"(a), "l"(b));
}
__device__ __forceinline__ uint32_t smem_u32(const void* p) {
    uint32_t a;
    asm("{ .reg .u64 t; cvta.to.shared.u64 t, %1; cvt.u32.u64 %0, t; }" : "=r"(a) : "l"(p));
    return a;
}
__device__ __forceinline__ void cpa16(uint32_t dst, const void* src) {
    asm volatile("cp.async.cg.shared.global [%0], [%1], 16;" :: "r"(dst), "l"(src));
}
// pack column id into low 12 mantissa bits of score
__device__ __forceinline__ float packf(float v, int col) {
    return __uint_as_float((__float_as_uint(v) & ~0xFFFu) | (unsigned)col);
}

// =====================================================================
// Kernel 1: projections (exact fp32) + fp16 emit + HALF the zero-fill
//   Fills output f4-cols [0,256) and [512,768) for its 64 rows (134MB).
// =====================================================================
#define XP 36

__global__ __launch_bounds__(256, 2) void proj_kernel(
        const float* __restrict__ x,
        const float* __restrict__ Wq,
        const float* __restrict__ Wk,
        float* __restrict__ out) {
    __shared__ float Xs[64*XP];
    __shared__ float Ws[128*XP];
    int t  = threadIdx.x;
    int rb = blockIdx.x;
    int b  = rb >> 6;
    int n0 = (rb & 63) << 6;
    int tx = t & 15, ty = t >> 4;
    int m0 = rb << 6;

    unsigned long long acc[4][8];
#pragma unroll
    for (int i = 0; i < 4; i++)
#pragma unroll
        for (int j = 0; j < 8; j++) acc[i][j] = 0ull;

    const float* xb = x + (size_t)(b*Nq + n0) * Cq;
    float4* out4 = (float4*)out;
    const float4 z4 = make_float4(0.f, 0.f, 0.f, 0.f);

    for (int c0 = 0; c0 < Cq; c0 += 32) {
        int it = c0 >> 5;                 // 0..7
#pragma unroll
        for (int s = 0; s < 2; s++) {
            int li = t + s*256;
            int r = li >> 3, cq = li & 7;
            float4 v = *(const float4*)(xb + (size_t)r*Cq + c0 + cq*4);
            *(float4*)(&Xs[r*XP + cq*4]) = v;
        }
#pragma unroll
        for (int s = 0; s < 16; s++) {
            int li  = t + s*256;
            int mat = li >> 11;
            int rem = li & 2047;
            int cc  = rem >> 6;
            int jj  = rem & 63;
            const float* W = mat ? Wk : Wq;
            Ws[(mat*64 + jj)*XP + cc] = W[(size_t)(c0+cc)*DKq + jj];
        }
        __syncthreads();

        // ---- zero-fill: 64 rows x 64 f4-cols this iter ----
        {
            int base = (it < 4) ? it*64 : 512 + (it - 4)*64;
#pragma unroll
            for (int s = 0; s < 16; s++) {
                int idx = t + s*256;          // 0..4095
                int r = idx >> 6, c = idx & 63;
                __stcs(&out4[(size_t)(m0 + r)*1024 + base + c], z4);
            }
        }

#pragma unroll
        for (int cc = 0; cc < 32; cc += 4) {
            ulonglong2 qv[4];
#pragma unroll
            for (int i = 0; i < 4; i++)
                qv[i] = *(const ulonglong2*)(&Xs[(ty + 16*i)*XP + cc]);
#pragma unroll
            for (int j = 0; j < 8; j++) {
                ulonglong2 wv = *(const ulonglong2*)(&Ws[(tx + 16*j)*XP + cc]);
#pragma unroll
                for (int i = 0; i < 4; i++) {
                    fma2(acc[i][j], qv[i].x, wv.x);
                    fma2(acc[i][j], qv[i].y, wv.y);
                }
            }
        }
        __syncthreads();
    }
#pragma unroll
    for (int i = 0; i < 4; i++) {
        size_t m = (size_t)rb*64 + ty + 16*i;
#pragma unroll
        for (int j = 0; j < 8; j++) {
            int col = tx + 16*j;
            union { unsigned long long u; float2 f; } cv; cv.u = acc[i][j];
            float v  = cv.f.x + cv.f.y;
            if (col < 64) {
                g_Qf[m*DKq + col] = v;
                g_Qh[m*DKq + col] = __float2half(v);
            } else {
                int k = col - 64;
                g_Kf[m*DKq + k] = v;
                g_Kh[m*DKq + k] = __float2half(v);
            }
        }
    }
}

// =====================================================================
// Kernel 2: fp16 approx GEMM + half zero-fill + top-8 streams
//   grid 512: (64-row block) x (2048-key half). 256 threads / 8 warps.
//   Fills f4-cols half*512 + [256,512) spread over 16 steps.
//   Epilogue: pair-merge then 4-way merge -> 8 candidates per row-half.
// =====================================================================
#define PH     72
#define PHB    144
#define PW     36
#define OFF_Q  0
#define QBYTES (64*PHB)                 // 9216
#define OFF_B0 QBYTES
#define BBYTES (128*PHB)                // 18432
#define OFF_B1 (OFF_B0 + BBYTES)
#define SMEM_EDGE (OFF_B1 + BBYTES)     // 46080

__device__ __forceinline__ void mma16(float c[4], uint32_t a0, uint32_t a1,
                                      uint32_t a2, uint32_t a3,
                                      uint32_t b0, uint32_t b1) {
    asm volatile(
        "mma.sync.aligned.m16n8k16.row.col.f32.f16.f16.f32 "
        "{%0,%1,%2,%3},{%4,%5,%6,%7},{%8,%9},{%0,%1,%2,%3};"
        : "+f"(c[0]), "+f"(c[1]), "+f"(c[2]), "+f"(c[3])
        : "r"(a0), "r"(a1), "r"(a2), "r"(a3), "r"(b0), "r"(b1));
}

__device__ __forceinline__ void ins8p(float* vals, float v, int col) {
    if (v > vals[7]) {
        float pv = packf(v, col);
#pragma unroll
        for (int q = 0; q < 8; q++) {
            if (pv > vals[q]) { float tv = vals[q]; vals[q] = pv; pv = tv; }
        }
    }
}

__global__ __launch_bounds__(256, 3)
void edge_kernel(float* __restrict__ out) {
    extern __shared__ __align__(16) char smem[];
    uint32_t sb = smem_u32(smem);
    const uint32_t* Qu = (const uint32_t*)(smem + OFF_Q);

    int tid = threadIdx.x;
    int wid = tid >> 5, lane = tid & 31;
    int g = lane >> 2, tg = lane & 3;
    int msub = wid >> 1, ksub = wid & 1;

    int bid  = blockIdx.x;
    int rb   = bid >> 1;
    int half = bid & 1;
    int m0    = rb * 64;
    int batch = rb >> 6;
    int key0  = half * 2048;

    // ---- load Q-half tile (64 x 64) ----
    const __half* qsrc = g_Qh + (size_t)m0 * DKq;
#pragma unroll
    for (int i = 0; i < 2; i++) {
        int idx = tid + i*256;
        int r = idx >> 3, c = idx & 7;
        cpa16(sb + OFF_Q + (uint32_t)(r*PHB + c*16), qsrc + (size_t)r*DKq + c*8);
    }
    asm volatile("cp.async.commit_group;");

    const __half* gK = g_Kh + (size_t)(batch*Nq + key0) * DKq;
#pragma unroll
    for (int i = 0; i < 4; i++) {
        int idx = tid + i*256;
        int r = idx >> 3, c = idx & 7;
        cpa16(sb + OFF_B0 + (uint32_t)(r*PHB + c*16), gK + (size_t)r*DKq + c*8);
    }
    asm volatile("cp.async.commit_group;");

    asm volatile("cp.async.wait_group 1;");
    __syncthreads();

    // ---- hoist A fragments: 16 regs ----
    uint32_t af[4][4];
    {
        int rr = msub*16 + g;
#pragma unroll
        for (int ks = 0; ks < 4; ks++) {
            af[ks][0] = Qu[rr*PW + ks*8 + tg];
            af[ks][1] = Qu[(rr + 8)*PW + ks*8 + tg];
            af[ks][2] = Qu[rr*PW + ks*8 + 4 + tg];
            af[ks][3] = Qu[(rr + 8)*PW + ks*8 + 4 + tg];
        }
    }

    float vals[2][8];
#pragma unroll
    for (int l = 0; l < 2; l++)
#pragma unroll
        for (int q = 0; q < 8; q++) vals[l][q] = NEG_BIG;

    float4* out4 = (float4*)out;
    const float4 z4 = make_float4(0.f, 0.f, 0.f, 0.f);

    for (int step = 0; step < 16; step++) {
        const uint32_t* Bu = (const uint32_t*)(smem + ((step & 1) ? OFF_B1 : OFF_B0));
        if (step < 15) {
            uint32_t boff = (step & 1) ? OFF_B0 : OFF_B1;
            const __half* src = gK + (size_t)(step + 1)*128*DKq;
#pragma unroll
            for (int i = 0; i < 4; i++) {
                int idx = tid + i*256;
                int r = idx >> 3, c = idx & 7;
                cpa16(sb + boff + (uint32_t)(r*PHB + c*16), src + (size_t)r*DKq + c*8);
            }
            asm volatile("cp.async.commit_group;");
            asm volatile("cp.async.wait_group 1;");
        } else {
            asm volatile("cp.async.wait_group 0;");
        }
        __syncthreads();

        // ---- zero-fill: 64 rows x 16 f4-cols this step ([256,512) range) ----
#pragma unroll
        for (int s = 0; s < 4; s++) {
            int idx = tid + s*256;          // 0..1023
            int r = idx >> 4, c = idx & 15;
            __stcs(&out4[(size_t)(m0 + r)*1024 + half*512 + 256 + step*16 + c], z4);
        }

        // ---- fp16 GEMM + scan, two j-halves (16 accum regs) ----
#pragma unroll
        for (int h = 0; h < 2; h++) {
            float c[4][4];
#pragma unroll
            for (int j = 0; j < 4; j++)
#pragma unroll
                for (int q = 0; q < 4; q++) c[j][q] = 0.f;

#pragma unroll
            for (int ks = 0; ks < 4; ks++) {
#pragma unroll
                for (int j = 0; j < 4; j++) {
                    int n = ksub*64 + (h*4 + j)*8 + g;
                    uint32_t b0 = Bu[n*PW + ks*8 + tg];
                    uint32_t b1 = Bu[n*PW + ks*8 + 4 + tg];
                    mma16(c[j], af[ks][0], af[ks][1], af[ks][2], af[ks][3], b0, b1);
                }
            }
#pragma unroll
            for (int j = 0; j < 4; j++) {
                int c0i = key0 + step*128 + ksub*64 + (h*4 + j)*8 + 2*tg;
                ins8p(vals[0], c[j][0], c0i);
                ins8p(vals[0], c[j][1], c0i + 1);
                ins8p(vals[1], c[j][2], c0i);
                ins8p(vals[1], c[j][3], c0i + 1);
            }
        }
        __syncthreads();
    }

    // ---- epilogue: dump -> pair-merge -> 4-way merge -> 8 cand/row-half ----
    float* MV  = (float*)(smem + OFF_B0);   // [64*4][17] = 17408B
    float* MV2 = (float*)(smem + OFF_B1);   // [64][33]   =  8448B
#pragma unroll
    for (int l = 0; l < 2; l++) {
        int rowLocal = msub*16 + l*8 + g;
#pragma unroll
        for (int q = 0; q < 8; q++)
            MV[(rowLocal*4 + tg)*17 + ksub*8 + q] = vals[l][q];
    }
    __syncthreads();
    {   // stage 1: 256 tasks, merge ksub pair (16 -> sorted 8)
        int rowLocal = tid >> 2, t4 = tid & 3;
        const float* A = &MV[(rowLocal*4 + t4)*17];
        float* O = &MV2[rowLocal*33 + t4*8];
        int pa = 0, pb = 8;
#pragma unroll
        for (int q = 0; q < 8; q++) {
            bool ta = (pa < 8) && (pb >= 16 || A[pa] >= A[pb]);
            O[q] = ta ? A[pa] : A[pb];
            if (ta) pa++; else pb++;
        }
    }
    __syncthreads();
    if (tid < 64) {  // stage 2: 4-way merge of sorted 8-lists -> top-8
        const float* Rw = &MV2[tid*33];
        int p0 = 0, p1 = 8, p2 = 16, p3 = 24;
        size_t base = (size_t)(m0 + tid)*16 + half*8;
#pragma unroll
        for (int sel = 0; sel < 8; sel++) {
            float b0 = (p0 < 8)  ? Rw[p0] : NEG_BIG;
            float b1 = (p1 < 16) ? Rw[p1] : NEG_BIG;
            float b2 = (p2 < 24) ? Rw[p2] : NEG_BIG;
            float b3 = (p3 < 32) ? Rw[p3] : NEG_BIG;
            float mm = fmaxf(fmaxf(b0, b1), fmaxf(b2, b3));
            g_cand[base + sel] = (int)(__float_as_uint(mm) & 0xFFFu);
            if      (mm == b0) p0++;
            else if (mm == b1) p1++;
            else if (mm == b2) p2++;
            else               p3++;
        }
    }
}

// =====================================================================
// Kernel 3: exact fp32 rescore of 16 candidates/row + top-8 + softmax
// =====================================================================
__global__ __launch_bounds__(256) void rescore_kernel(float* __restrict__ out) {
    __shared__ float sd[8][16];
    int tid = threadIdx.x;
    int w = tid >> 5, lane = tid & 31;
    int row   = blockIdx.x*8 + w;
    int batch = row >> 12;
    int hl = lane & 15;

    const float* Kf = g_Kf + (size_t)batch * Nq * DKq;
    float4 qv = *(const float4*)(g_Qf + (size_t)row*DKq + hl*4);

    int c0 = g_cand[(size_t)row*16 + hl];

#pragma unroll
    for (int it = 0; it < 8; it++) {
        int j = 2*it + (lane >> 4);
        int cnd = __shfl_sync(0xFFFFFFFFu, c0, j);
        float4 kv = *(const float4*)(Kf + (size_t)cnd*DKq + hl*4);
        float p = qv.x*kv.x + qv.y*kv.y + qv.z*kv.z + qv.w*kv.w;
        p += __shfl_xor_sync(0xFFFFFFFFu, p, 1);
        p += __shfl_xor_sync(0xFFFFFFFFu, p, 2);
        p += __shfl_xor_sync(0xFFFFFFFFu, p, 4);
        p += __shfl_xor_sync(0xFFFFFFFFu, p, 8);
        if (hl == 0) sd[w][j] = p;
    }
    __syncwarp();

    float s0 = sd[w][hl];     // duplicated across lane halves
    int   i0 = c0;

    float bv[8]; int bi[8];
#pragma unroll
    for (int sel = 0; sel < 8; sel++) {
        float v = s0; int ix = i0;
#pragma unroll
        for (int off = 16; off > 0; off >>= 1) {
            float vv = __shfl_xor_sync(0xFFFFFFFFu, v, off);
            int   ii = __shfl_xor_sync(0xFFFFFFFFu, ix, off);
            if (vv > v || (vv == v && ii < ix)) { v = vv; ix = ii; }
        }
        bv[sel] = v; bi[sel] = ix;
        if (i0 == ix) s0 = NEG_BIG;
    }

    float mx = bv[0];
    float Z = 0.f, e[8];
#pragma unroll
    for (int q = 0; q < 8; q++) { e[q] = expf(0.125f*(bv[q] - mx)); Z += e[q]; }
    float inv = 1.0f / Z;
    if (lane < 8)
        out[(size_t)row*Nq + bi[lane]] = e[lane] * inv;
}

// =====================================================================
extern "C" void kernel_launch(void* const* d_in, const int* in_sizes, int n_in,
                              void* d_out, int out_size) {
    const float* x  = (const float*)d_in[0];
    const float* Wq = (const float*)d_in[1];
    const float* Wk = (const float*)d_in[2];
    float* out = (float*)d_out;

    cudaFuncSetAttribute(edge_kernel,
                         cudaFuncAttributeMaxDynamicSharedMemorySize, SMEM_EDGE);

    proj_kernel<<<NROWS/64, 256>>>(x, Wq, Wk, out);
    edge_kernel<<<NROWS/32, 256, SMEM_EDGE>>>(out);   // 512 CTAs
    rescore_kernel<<<NROWS/8, 256>>>(out);
}

// round 15
// speedup vs baseline: 1.7687x; 1.4635x over previous
#include <cuda_runtime.h>
#include <cuda_fp16.h>
#include <cstdint>
#include <math.h>

#define Bq   4
#define Nq   4096
#define Cq   256
#define DKq  64
#define NROWS (Bq*Nq)          // 16384
#define NEG_BIG (-3.402823466e38f)

__device__ float  g_Qf[NROWS*DKq];
__device__ float  g_Kf[NROWS*DKq];
__device__ __half g_Qh[NROWS*DKq];
__device__ __half g_Kh[NROWS*DKq];
__device__ int    g_cand[NROWS*16];     // 16 candidate cols per row

__device__ __forceinline__ void fma2(unsigned long long &acc,
                                     unsigned long long a, unsigned long long b) {
    asm volatile("fma.rn.f32x2 %0, %1, %2, %0;" : "+l"(acc) : "l"(a), "l"(b));
}
__device__ __forceinline__ uint32_t smem_u32(const void* p) {
    uint32_t a;
    asm("{ .reg .u64 t; cvta.to.shared.u64 t, %1; cvt.u32.u64 %0, t; }" : "=r"(a) : "l"(p));
    return a;
}
__device__ __forceinline__ void cpa16(uint32_t dst, const void* src) {
    asm volatile("cp.async.cg.shared.global [%0], [%1], 16;" :: "r"(dst), "l"(src));
}
// pack column id into low 12 mantissa bits of score
__device__ __forceinline__ float packf(float v, int col) {
    return __uint_as_float((__float_as_uint(v) & ~0xFFFu) | (unsigned)col);
}

// ---- branchless desc compare-exchange + networks ----
__device__ __forceinline__ void ce(float& a, float& b) {
    float mx = fmaxf(a, b); b = fminf(a, b); a = mx;
}
// Batcher odd-even merge sort, 8 elements desc, 19 CE
__device__ __forceinline__ void sort8(float* s) {
    ce(s[0],s[1]); ce(s[2],s[3]); ce(s[4],s[5]); ce(s[6],s[7]);
    ce(s[0],s[2]); ce(s[1],s[3]); ce(s[4],s[6]); ce(s[5],s[7]);
    ce(s[1],s[2]); ce(s[5],s[6]);
    ce(s[0],s[4]); ce(s[1],s[5]); ce(s[2],s[6]); ce(s[3],s[7]);
    ce(s[2],s[4]); ce(s[3],s[5]);
    ce(s[1],s[2]); ce(s[3],s[4]); ce(s[5],s[6]);
}
// vals desc, s desc -> vals = top-8 desc of union (8 max + 12-CE bitonic clean)
__device__ __forceinline__ void merge8(float* vals, const float* s) {
    float t[8];
#pragma unroll
    for (int i = 0; i < 8; i++) t[i] = fmaxf(vals[i], s[7 - i]);
    ce(t[0],t[4]); ce(t[1],t[5]); ce(t[2],t[6]); ce(t[3],t[7]);
    ce(t[0],t[2]); ce(t[1],t[3]); ce(t[4],t[6]); ce(t[5],t[7]);
    ce(t[0],t[1]); ce(t[2],t[3]); ce(t[4],t[5]); ce(t[6],t[7]);
#pragma unroll
    for (int i = 0; i < 8; i++) vals[i] = t[i];
}

// =====================================================================
// Kernel 1: projections (exact fp32) + fp16 emit + HALF the zero-fill
// =====================================================================
#define XP 36

__global__ __launch_bounds__(256, 2) void proj_kernel(
        const float* __restrict__ x,
        const float* __restrict__ Wq,
        const float* __restrict__ Wk,
        float* __restrict__ out) {
    __shared__ float Xs[64*XP];
    __shared__ float Ws[128*XP];
    int t  = threadIdx.x;
    int rb = blockIdx.x;
    int b  = rb >> 6;
    int n0 = (rb & 63) << 6;
    int tx = t & 15, ty = t >> 4;
    int m0 = rb << 6;

    unsigned long long acc[4][8];
#pragma unroll
    for (int i = 0; i < 4; i++)
#pragma unroll
        for (int j = 0; j < 8; j++) acc[i][j] = 0ull;

    const float* xb = x + (size_t)(b*Nq + n0) * Cq;
    float4* out4 = (float4*)out;
    const float4 z4 = make_float4(0.f, 0.f, 0.f, 0.f);

    for (int c0 = 0; c0 < Cq; c0 += 32) {
        int it = c0 >> 5;
#pragma unroll
        for (int s = 0; s < 2; s++) {
            int li = t + s*256;
            int r = li >> 3, cq = li & 7;
            float4 v = *(const float4*)(xb + (size_t)r*Cq + c0 + cq*4);
            *(float4*)(&Xs[r*XP + cq*4]) = v;
        }
#pragma unroll
        for (int s = 0; s < 16; s++) {
            int li  = t + s*256;
            int mat = li >> 11;
            int rem = li & 2047;
            int cc  = rem >> 6;
            int jj  = rem & 63;
            const float* W = mat ? Wk : Wq;
            Ws[(mat*64 + jj)*XP + cc] = W[(size_t)(c0+cc)*DKq + jj];
        }
        __syncthreads();

        {   // zero-fill: 64 rows x 64 f4-cols this iter
            int base = (it < 4) ? it*64 : 512 + (it - 4)*64;
#pragma unroll
            for (int s = 0; s < 16; s++) {
                int idx = t + s*256;
                int r = idx >> 6, c = idx & 63;
                __stcs(&out4[(size_t)(m0 + r)*1024 + base + c], z4);
            }
        }

#pragma unroll
        for (int cc = 0; cc < 32; cc += 4) {
            ulonglong2 qv[4];
#pragma unroll
            for (int i = 0; i < 4; i++)
                qv[i] = *(const ulonglong2*)(&Xs[(ty + 16*i)*XP + cc]);
#pragma unroll
            for (int j = 0; j < 8; j++) {
                ulonglong2 wv = *(const ulonglong2*)(&Ws[(tx + 16*j)*XP + cc]);
#pragma unroll
                for (int i = 0; i < 4; i++) {
                    fma2(acc[i][j], qv[i].x, wv.x);
                    fma2(acc[i][j], qv[i].y, wv.y);
                }
            }
        }
        __syncthreads();
    }
#pragma unroll
    for (int i = 0; i < 4; i++) {
        size_t m = (size_t)rb*64 + ty + 16*i;
#pragma unroll
        for (int j = 0; j < 8; j++) {
            int col = tx + 16*j;
            union { unsigned long long u; float2 f; } cv; cv.u = acc[i][j];
            float v  = cv.f.x + cv.f.y;
            if (col < 64) {
                g_Qf[m*DKq + col] = v;
                g_Qh[m*DKq + col] = __float2half(v);
            } else {
                int k = col - 64;
                g_Kf[m*DKq + k] = v;
                g_Kh[m*DKq + k] = __float2half(v);
            }
        }
    }
}

// =====================================================================
// Kernel 2: fp16 approx GEMM + half zero-fill + BRANCHLESS top-8 streams
// =====================================================================
#define PH     72
#define PHB    144
#define PW     36
#define OFF_Q  0
#define QBYTES (64*PHB)                 // 9216
#define OFF_B0 QBYTES
#define BBYTES (128*PHB)                // 18432
#define OFF_B1 (OFF_B0 + BBYTES)
#define SMEM_EDGE (OFF_B1 + BBYTES)     // 46080

__device__ __forceinline__ void mma16(float c[4], uint32_t a0, uint32_t a1,
                                      uint32_t a2, uint32_t a3,
                                      uint32_t b0, uint32_t b1) {
    asm volatile(
        "mma.sync.aligned.m16n8k16.row.col.f32.f16.f16.f32 "
        "{%0,%1,%2,%3},{%4,%5,%6,%7},{%8,%9},{%0,%1,%2,%3};"
        : "+f"(c[0]), "+f"(c[1]), "+f"(c[2]), "+f"(c[3])
        : "r"(a0), "r"(a1), "r"(a2), "r"(a3), "r"(b0), "r"(b1));
}

__global__ __launch_bounds__(256, 3)
void edge_kernel(float* __restrict__ out) {
    extern __shared__ __align__(16) char smem[];
    uint32_t sb = smem_u32(smem);
    const uint32_t* Qu = (const uint32_t*)(smem + OFF_Q);

    int tid = threadIdx.x;
    int wid = tid >> 5, lane = tid & 31;
    int g = lane >> 2, tg = lane & 3;
    int msub = wid >> 1, ksub = wid & 1;

    int bid  = blockIdx.x;
    int rb   = bid >> 1;
    int half = bid & 1;
    int m0    = rb * 64;
    int batch = rb >> 6;
    int key0  = half * 2048;

    // ---- load Q-half tile (64 x 64) ----
    const __half* qsrc = g_Qh + (size_t)m0 * DKq;
#pragma unroll
    for (int i = 0; i < 2; i++) {
        int idx = tid + i*256;
        int r = idx >> 3, c = idx & 7;
        cpa16(sb + OFF_Q + (uint32_t)(r*PHB + c*16), qsrc + (size_t)r*DKq + c*8);
    }
    asm volatile("cp.async.commit_group;");

    const __half* gK = g_Kh + (size_t)(batch*Nq + key0) * DKq;
#pragma unroll
    for (int i = 0; i < 4; i++) {
        int idx = tid + i*256;
        int r = idx >> 3, c = idx & 7;
        cpa16(sb + OFF_B0 + (uint32_t)(r*PHB + c*16), gK + (size_t)r*DKq + c*8);
    }
    asm volatile("cp.async.commit_group;");

    asm volatile("cp.async.wait_group 1;");
    __syncthreads();

    // ---- hoist A fragments: 16 regs ----
    uint32_t af[4][4];
    {
        int rr = msub*16 + g;
#pragma unroll
        for (int ks = 0; ks < 4; ks++) {
            af[ks][0] = Qu[rr*PW + ks*8 + tg];
            af[ks][1] = Qu[(rr + 8)*PW + ks*8 + tg];
            af[ks][2] = Qu[rr*PW + ks*8 + 4 + tg];
            af[ks][3] = Qu[(rr + 8)*PW + ks*8 + 4 + tg];
        }
    }

    float vals[2][8];
#pragma unroll
    for (int l = 0; l < 2; l++)
#pragma unroll
        for (int q = 0; q < 8; q++) vals[l][q] = NEG_BIG;

    float4* out4 = (float4*)out;
    const float4 z4 = make_float4(0.f, 0.f, 0.f, 0.f);

    for (int step = 0; step < 16; step++) {
        const uint32_t* Bu = (const uint32_t*)(smem + ((step & 1) ? OFF_B1 : OFF_B0));
        if (step < 15) {
            uint32_t boff = (step & 1) ? OFF_B0 : OFF_B1;
            const __half* src = gK + (size_t)(step + 1)*128*DKq;
#pragma unroll
            for (int i = 0; i < 4; i++) {
                int idx = tid + i*256;
                int r = idx >> 3, c = idx & 7;
                cpa16(sb + boff + (uint32_t)(r*PHB + c*16), src + (size_t)r*DKq + c*8);
            }
            asm volatile("cp.async.commit_group;");
            asm volatile("cp.async.wait_group 1;");
        } else {
            asm volatile("cp.async.wait_group 0;");
        }
        __syncthreads();

        // ---- zero-fill: 64 rows x 16 f4-cols this step ----
#pragma unroll
        for (int s = 0; s < 4; s++) {
            int idx = tid + s*256;
            int r = idx >> 4, c = idx & 15;
            __stcs(&out4[(size_t)(m0 + r)*1024 + half*512 + 256 + step*16 + c], z4);
        }

        // ---- fp16 GEMM + branchless network scan, two j-halves ----
#pragma unroll
        for (int h = 0; h < 2; h++) {
            float c[4][4];
#pragma unroll
            for (int j = 0; j < 4; j++)
#pragma unroll
                for (int q = 0; q < 4; q++) c[j][q] = 0.f;

#pragma unroll
            for (int ks = 0; ks < 4; ks++) {
#pragma unroll
                for (int j = 0; j < 4; j++) {
                    int n = ksub*64 + (h*4 + j)*8 + g;
                    uint32_t b0 = Bu[n*PW + ks*8 + tg];
                    uint32_t b1 = Bu[n*PW + ks*8 + 4 + tg];
                    mma16(c[j], af[ks][0], af[ks][1], af[ks][2], af[ks][3], b0, b1);
                }
            }
            // pack 8 new values per stream, sort desc, merge into running top-8
            float s0[8], s1[8];
#pragma unroll
            for (int j = 0; j < 4; j++) {
                int c0i = key0 + step*128 + ksub*64 + (h*4 + j)*8 + 2*tg;
                s0[2*j]   = packf(c[j][0], c0i);
                s0[2*j+1] = packf(c[j][1], c0i + 1);
                s1[2*j]   = packf(c[j][2], c0i);
                s1[2*j+1] = packf(c[j][3], c0i + 1);
            }
            sort8(s0); merge8(vals[0], s0);
            sort8(s1); merge8(vals[1], s1);
        }
        __syncthreads();
    }

    // ---- epilogue: dump -> pair-merge -> 4-way merge -> 8 cand/row-half ----
    float* MV  = (float*)(smem + OFF_B0);   // [64*4][17] = 17408B
    float* MV2 = (float*)(smem + OFF_B1);   // [64][33]   =  8448B
#pragma unroll
    for (int l = 0; l < 2; l++) {
        int rowLocal = msub*16 + l*8 + g;
#pragma unroll
        for (int q = 0; q < 8; q++)
            MV[(rowLocal*4 + tg)*17 + ksub*8 + q] = vals[l][q];
    }
    __syncthreads();
    {   // stage 1: merge ksub pair (two sorted 8s -> sorted top-8)
        int rowLocal = tid >> 2, t4 = tid & 3;
        const float* A = &MV[(rowLocal*4 + t4)*17];
        float* O = &MV2[rowLocal*33 + t4*8];
        int pa = 0, pb = 8;
#pragma unroll
        for (int q = 0; q < 8; q++) {
            bool ta = (pa < 8) && (pb >= 16 || A[pa] >= A[pb]);
            O[q] = ta ? A[pa] : A[pb];
            if (ta) pa++; else pb++;
        }
    }
    __syncthreads();
    if (tid < 64) {  // stage 2: 4-way merge of sorted 8-lists -> top-8
        const float* Rw = &MV2[tid*33];
        int p0 = 0, p1 = 8, p2 = 16, p3 = 24;
        size_t base = (size_t)(m0 + tid)*16 + half*8;
#pragma unroll
        for (int sel = 0; sel < 8; sel++) {
            float b0 = (p0 < 8)  ? Rw[p0] : NEG_BIG;
            float b1 = (p1 < 16) ? Rw[p1] : NEG_BIG;
            float b2 = (p2 < 24) ? Rw[p2] : NEG_BIG;
            float b3 = (p3 < 32) ? Rw[p3] : NEG_BIG;
            float mm = fmaxf(fmaxf(b0, b1), fmaxf(b2, b3));
            g_cand[base + sel] = (int)(__float_as_uint(mm) & 0xFFFu);
            if      (mm == b0) p0++;
            else if (mm == b1) p1++;
            else if (mm == b2) p2++;
            else               p3++;
        }
    }
}

// =====================================================================
// Kernel 3: exact fp32 rescore of 16 candidates/row + top-8 + softmax
// =====================================================================
__global__ __launch_bounds__(256) void rescore_kernel(float* __restrict__ out) {
    __shared__ float sd[8][16];
    int tid = threadIdx.x;
    int w = tid >> 5, lane = tid & 31;
    int row   = blockIdx.x*8 + w;
    int batch = row >> 12;
    int hl = lane & 15;

    const float* Kf = g_Kf + (size_t)batch * Nq * DKq;
    float4 qv = *(const float4*)(g_Qf + (size_t)row*DKq + hl*4);

    int c0 = g_cand[(size_t)row*16 + hl];

#pragma unroll
    for (int it = 0; it < 8; it++) {
        int j = 2*it + (lane >> 4);
        int cnd = __shfl_sync(0xFFFFFFFFu, c0, j);
        float4 kv = *(const float4*)(Kf + (size_t)cnd*DKq + hl*4);
        float p = qv.x*kv.x + qv.y*kv.y + qv.z*kv.z + qv.w*kv.w;
        p += __shfl_xor_sync(0xFFFFFFFFu, p, 1);
        p += __shfl_xor_sync(0xFFFFFFFFu, p, 2);
        p += __shfl_xor_sync(0xFFFFFFFFu, p, 4);
        p += __shfl_xor_sync(0xFFFFFFFFu, p, 8);
        if (hl == 0) sd[w][j] = p;
    }
    __syncwarp();

    float s0 = sd[w][hl];
    int   i0 = c0;

    float bv[8]; int bi[8];
#pragma unroll
    for (int sel = 0; sel < 8; sel++) {
        float v = s0; int ix = i0;
#pragma unroll
        for (int off = 16; off > 0; off >>= 1) {
            float vv = __shfl_xor_sync(0xFFFFFFFFu, v, off);
            int   ii = __shfl_xor_sync(0xFFFFFFFFu, ix, off);
            if (vv > v || (vv == v && ii < ix)) { v = vv; ix = ii; }
        }
        bv[sel] = v; bi[sel] = ix;
        if (i0 == ix) s0 = NEG_BIG;
    }

    float mx = bv[0];
    float Z = 0.f, e[8];
#pragma unroll
    for (int q = 0; q < 8; q++) { e[q] = expf(0.125f*(bv[q] - mx)); Z += e[q]; }
    float inv = 1.0f / Z;
    if (lane < 8)
        out[(size_t)row*Nq + bi[lane]] = e[lane] * inv;
}

// =====================================================================
extern "C" void kernel_launch(void* const* d_in, const int* in_sizes, int n_in,
                              void* d_out, int out_size) {
    const float* x  = (const float*)d_in[0];
    const float* Wq = (const float*)d_in[1];
    const float* Wk = (const float*)d_in[2];
    float* out = (float*)d_out;

    cudaFuncSetAttribute(edge_kernel,
                         cudaFuncAttributeMaxDynamicSharedMemorySize, SMEM_EDGE);

    proj_kernel<<<NROWS/64, 256>>>(x, Wq, Wk, out);
    edge_kernel<<<NROWS/32, 256, SMEM_EDGE>>>(out);   // 512 CTAs
    rescore_kernel<<<NROWS/8, 256>>>(out);
}

// round 16
// speedup vs baseline: 1.8915x; 1.0694x over previous
#include <cuda_runtime.h>
#include <cuda_fp16.h>
#include <cstdint>
#include <math.h>

#define Bq   4
#define Nq   4096
#define Cq   256
#define DKq  64
#define NROWS (Bq*Nq)          // 16384
#define NEG_BIG (-3.402823466e38f)

__device__ float  g_Qf[NROWS*DKq];
__device__ float  g_Kf[NROWS*DKq];
__device__ __half g_Qh[NROWS*DKq];
__device__ __half g_Kh[NROWS*DKq];
__device__ int    g_cand[NROWS*16];     // 16 candidate cols per row

__device__ __forceinline__ void fma2(unsigned long long &acc,
                                     unsigned long long a, unsigned long long b) {
    asm volatile("fma.rn.f32x2 %0, %1, %2, %0;" : "+l"(acc) : "l"(a), "l"(b));
}
__device__ __forceinline__ uint32_t smem_u32(const void* p) {
    uint32_t a;
    asm("{ .reg .u64 t; cvta.to.shared.u64 t, %1; cvt.u32.u64 %0, t; }" : "=r"(a) : "l"(p));
    return a;
}
__device__ __forceinline__ void cpa16(uint32_t dst, const void* src) {
    asm volatile("cp.async.cg.shared.global [%0], [%1], 16;" :: "r"(dst), "l"(src));
}
// pack column id into low 12 mantissa bits of score
__device__ __forceinline__ float packf(float v, int col) {
    return __uint_as_float((__float_as_uint(v) & ~0xFFFu) | (unsigned)col);
}

// ---- branchless desc compare-exchange + networks ----
__device__ __forceinline__ void ce(float& a, float& b) {
    float mx = fmaxf(a, b); b = fminf(a, b); a = mx;
}
// Batcher odd-even merge sort, 8 elements desc, 19 CE
__device__ __forceinline__ void sort8(float* s) {
    ce(s[0],s[1]); ce(s[2],s[3]); ce(s[4],s[5]); ce(s[6],s[7]);
    ce(s[0],s[2]); ce(s[1],s[3]); ce(s[4],s[6]); ce(s[5],s[7]);
    ce(s[1],s[2]); ce(s[5],s[6]);
    ce(s[0],s[4]); ce(s[1],s[5]); ce(s[2],s[6]); ce(s[3],s[7]);
    ce(s[2],s[4]); ce(s[3],s[5]);
    ce(s[1],s[2]); ce(s[3],s[4]); ce(s[5],s[6]);
}
// vals desc, s desc -> vals = top-8 desc of union (8 max + 12-CE bitonic clean)
__device__ __forceinline__ void merge8(float* vals, const float* s) {
    float t[8];
#pragma unroll
    for (int i = 0; i < 8; i++) t[i] = fmaxf(vals[i], s[7 - i]);
    ce(t[0],t[4]); ce(t[1],t[5]); ce(t[2],t[6]); ce(t[3],t[7]);
    ce(t[0],t[2]); ce(t[1],t[3]); ce(t[4],t[6]); ce(t[5],t[7]);
    ce(t[0],t[1]); ce(t[2],t[3]); ce(t[4],t[5]); ce(t[6],t[7]);
#pragma unroll
    for (int i = 0; i < 8; i++) vals[i] = t[i];
}

// =====================================================================
// Kernel 1: projections (exact fp32) + fp16 emit + HALF the zero-fill
// =====================================================================
#define XP 36

__global__ __launch_bounds__(256, 2) void proj_kernel(
        const float* __restrict__ x,
        const float* __restrict__ Wq,
        const float* __restrict__ Wk,
        float* __restrict__ out) {
    __shared__ float Xs[64*XP];
    __shared__ float Ws[128*XP];
    int t  = threadIdx.x;
    int rb = blockIdx.x;
    int b  = rb >> 6;
    int n0 = (rb & 63) << 6;
    int tx = t & 15, ty = t >> 4;
    int m0 = rb << 6;

    unsigned long long acc[4][8];
#pragma unroll
    for (int i = 0; i < 4; i++)
#pragma unroll
        for (int j = 0; j < 8; j++) acc[i][j] = 0ull;

    const float* xb = x + (size_t)(b*Nq + n0) * Cq;
    float4* out4 = (float4*)out;
    const float4 z4 = make_float4(0.f, 0.f, 0.f, 0.f);

    for (int c0 = 0; c0 < Cq; c0 += 32) {
        int it = c0 >> 5;
#pragma unroll
        for (int s = 0; s < 2; s++) {
            int li = t + s*256;
            int r = li >> 3, cq = li & 7;
            float4 v = *(const float4*)(xb + (size_t)r*Cq + c0 + cq*4);
            *(float4*)(&Xs[r*XP + cq*4]) = v;
        }
#pragma unroll
        for (int s = 0; s < 16; s++) {
            int li  = t + s*256;
            int mat = li >> 11;
            int rem = li & 2047;
            int cc  = rem >> 6;
            int jj  = rem & 63;
            const float* W = mat ? Wk : Wq;
            Ws[(mat*64 + jj)*XP + cc] = W[(size_t)(c0+cc)*DKq + jj];
        }
        __syncthreads();

        {   // zero-fill: 64 rows x 64 f4-cols this iter
            int base = (it < 4) ? it*64 : 512 + (it - 4)*64;
#pragma unroll
            for (int s = 0; s < 16; s++) {
                int idx = t + s*256;
                int r = idx >> 6, c = idx & 63;
                __stcs(&out4[(size_t)(m0 + r)*1024 + base + c], z4);
            }
        }

#pragma unroll
        for (int cc = 0; cc < 32; cc += 4) {
            ulonglong2 qv[4];
#pragma unroll
            for (int i = 0; i < 4; i++)
                qv[i] = *(const ulonglong2*)(&Xs[(ty + 16*i)*XP + cc]);
#pragma unroll
            for (int j = 0; j < 8; j++) {
                ulonglong2 wv = *(const ulonglong2*)(&Ws[(tx + 16*j)*XP + cc]);
#pragma unroll
                for (int i = 0; i < 4; i++) {
                    fma2(acc[i][j], qv[i].x, wv.x);
                    fma2(acc[i][j], qv[i].y, wv.y);
                }
            }
        }
        __syncthreads();
    }
#pragma unroll
    for (int i = 0; i < 4; i++) {
        size_t m = (size_t)rb*64 + ty + 16*i;
#pragma unroll
        for (int j = 0; j < 8; j++) {
            int col = tx + 16*j;
            union { unsigned long long u; float2 f; } cv; cv.u = acc[i][j];
            float v  = cv.f.x + cv.f.y;
            if (col < 64) {
                g_Qf[m*DKq + col] = v;
                g_Qh[m*DKq + col] = __float2half(v);
            } else {
                int k = col - 64;
                g_Kf[m*DKq + k] = v;
                g_Kh[m*DKq + k] = __float2half(v);
            }
        }
    }
}

// =====================================================================
// Kernel 2: fp16 GEMM + software-pipelined branchless top-8 scan
//   scan of h-half lags one MMA behind -> fma overlaps tensor pipe.
// =====================================================================
#define PH     72
#define PHB    144
#define PW     36
#define OFF_Q  0
#define QBYTES (64*PHB)                 // 9216
#define OFF_B0 QBYTES
#define BBYTES (128*PHB)                // 18432
#define OFF_B1 (OFF_B0 + BBYTES)
#define SMEM_EDGE (OFF_B1 + BBYTES)     // 46080

__device__ __forceinline__ void mma16(float c[4], uint32_t a0, uint32_t a1,
                                      uint32_t a2, uint32_t a3,
                                      uint32_t b0, uint32_t b1) {
    asm volatile(
        "mma.sync.aligned.m16n8k16.row.col.f32.f16.f16.f32 "
        "{%0,%1,%2,%3},{%4,%5,%6,%7},{%8,%9},{%0,%1,%2,%3};"
        : "+f"(c[0]), "+f"(c[1]), "+f"(c[2]), "+f"(c[3])
        : "r"(a0), "r"(a1), "r"(a2), "r"(a3), "r"(b0), "r"(b1));
}

// scan one accumulator set (4 j-frags) into the two stream top-8 lists
__device__ __forceinline__ void scan_set(const float c[4][4], int base, int tg,
                                         float* v0, float* v1) {
    float s0[8], s1[8];
#pragma unroll
    for (int j = 0; j < 4; j++) {
        int ci = base + j*8 + 2*tg;
        s0[2*j]   = packf(c[j][0], ci);
        s0[2*j+1] = packf(c[j][1], ci + 1);
        s1[2*j]   = packf(c[j][2], ci);
        s1[2*j+1] = packf(c[j][3], ci + 1);
    }
    sort8(s0); merge8(v0, s0);
    sort8(s1); merge8(v1, s1);
}

__global__ __launch_bounds__(256, 2)
void edge_kernel(float* __restrict__ out) {
    extern __shared__ __align__(16) char smem[];
    uint32_t sb = smem_u32(smem);
    const uint32_t* Qu = (const uint32_t*)(smem + OFF_Q);

    int tid = threadIdx.x;
    int wid = tid >> 5, lane = tid & 31;
    int g = lane >> 2, tg = lane & 3;
    int msub = wid >> 1, ksub = wid & 1;

    int bid  = blockIdx.x;
    int rb   = bid >> 1;
    int half = bid & 1;
    int m0    = rb * 64;
    int batch = rb >> 6;
    int key0  = half * 2048;

    // ---- load Q-half tile (64 x 64) ----
    const __half* qsrc = g_Qh + (size_t)m0 * DKq;
#pragma unroll
    for (int i = 0; i < 2; i++) {
        int idx = tid + i*256;
        int r = idx >> 3, c = idx & 7;
        cpa16(sb + OFF_Q + (uint32_t)(r*PHB + c*16), qsrc + (size_t)r*DKq + c*8);
    }
    asm volatile("cp.async.commit_group;");

    const __half* gK = g_Kh + (size_t)(batch*Nq + key0) * DKq;
#pragma unroll
    for (int i = 0; i < 4; i++) {
        int idx = tid + i*256;
        int r = idx >> 3, c = idx & 7;
        cpa16(sb + OFF_B0 + (uint32_t)(r*PHB + c*16), gK + (size_t)r*DKq + c*8);
    }
    asm volatile("cp.async.commit_group;");

    asm volatile("cp.async.wait_group 1;");
    __syncthreads();

    // ---- hoist A fragments: 16 regs ----
    uint32_t af[4][4];
    {
        int rr = msub*16 + g;
#pragma unroll
        for (int ks = 0; ks < 4; ks++) {
            af[ks][0] = Qu[rr*PW + ks*8 + tg];
            af[ks][1] = Qu[(rr + 8)*PW + ks*8 + tg];
            af[ks][2] = Qu[rr*PW + ks*8 + 4 + tg];
            af[ks][3] = Qu[(rr + 8)*PW + ks*8 + 4 + tg];
        }
    }

    float vals[2][8];
#pragma unroll
    for (int l = 0; l < 2; l++)
#pragma unroll
        for (int q = 0; q < 8; q++) vals[l][q] = NEG_BIG;

    float4* out4 = (float4*)out;
    const float4 z4 = make_float4(0.f, 0.f, 0.f, 0.f);

    // pending accumulator set (h1 of previous step); init harmless
    float cB[4][4];
#pragma unroll
    for (int j = 0; j < 4; j++)
#pragma unroll
        for (int q = 0; q < 4; q++) cB[j][q] = NEG_BIG;
    int pendBase = key0 + ksub*64;      // any valid col base; values are NEG_BIG

    for (int step = 0; step < 16; step++) {
        const uint32_t* Bu = (const uint32_t*)(smem + ((step & 1) ? OFF_B1 : OFF_B0));
        if (step < 15) {
            uint32_t boff = (step & 1) ? OFF_B0 : OFF_B1;
            const __half* src = gK + (size_t)(step + 1)*128*DKq;
#pragma unroll
            for (int i = 0; i < 4; i++) {
                int idx = tid + i*256;
                int r = idx >> 3, c = idx & 7;
                cpa16(sb + boff + (uint32_t)(r*PHB + c*16), src + (size_t)r*DKq + c*8);
            }
            asm volatile("cp.async.commit_group;");
            asm volatile("cp.async.wait_group 1;");
        } else {
            asm volatile("cp.async.wait_group 0;");
        }
        __syncthreads();

        int sbase = key0 + step*128 + ksub*64;

        // ---- MMA h0 -> cA ----
        float cA[4][4];
#pragma unroll
        for (int j = 0; j < 4; j++)
#pragma unroll
            for (int q = 0; q < 4; q++) cA[j][q] = 0.f;
#pragma unroll
        for (int ks = 0; ks < 4; ks++)
#pragma unroll
            for (int j = 0; j < 4; j++) {
                int n = ksub*64 + j*8 + g;
                uint32_t b0 = Bu[n*PW + ks*8 + tg];
                uint32_t b1 = Bu[n*PW + ks*8 + 4 + tg];
                mma16(cA[j], af[ks][0], af[ks][1], af[ks][2], af[ks][3], b0, b1);
            }

        // ---- scan pending (previous step h1) — overlaps MMA h0 latency ----
        scan_set(cB, pendBase, tg, vals[0], vals[1]);

        // ---- zero-fill: 64 rows x 16 f4-cols this step ----
#pragma unroll
        for (int s = 0; s < 4; s++) {
            int idx = tid + s*256;
            int r = idx >> 4, c = idx & 15;
            __stcs(&out4[(size_t)(m0 + r)*1024 + half*512 + 256 + step*16 + c], z4);
        }

        // ---- MMA h1 -> cB ----
#pragma unroll
        for (int j = 0; j < 4; j++)
#pragma unroll
            for (int q = 0; q < 4; q++) cB[j][q] = 0.f;
#pragma unroll
        for (int ks = 0; ks < 4; ks++)
#pragma unroll
            for (int j = 0; j < 4; j++) {
                int n = ksub*64 + (4 + j)*8 + g;
                uint32_t b0 = Bu[n*PW + ks*8 + tg];
                uint32_t b1 = Bu[n*PW + ks*8 + 4 + tg];
                mma16(cB[j], af[ks][0], af[ks][1], af[ks][2], af[ks][3], b0, b1);
            }

        // ---- scan cA (this step h0) — overlaps MMA h1 latency ----
        scan_set(cA, sbase, tg, vals[0], vals[1]);
        pendBase = sbase + 32;
        __syncthreads();
    }
    // drain last pending set
    scan_set(cB, pendBase, tg, vals[0], vals[1]);

    // ---- epilogue: dump -> pair-merge -> 4-way merge -> 8 cand/row-half ----
    float* MV  = (float*)(smem + OFF_B0);   // [64*4][17] = 17408B
    float* MV2 = (float*)(smem + OFF_B1);   // [64][33]   =  8448B
    __syncthreads();
#pragma unroll
    for (int l = 0; l < 2; l++) {
        int rowLocal = msub*16 + l*8 + g;
#pragma unroll
        for (int q = 0; q < 8; q++)
            MV[(rowLocal*4 + tg)*17 + ksub*8 + q] = vals[l][q];
    }
    __syncthreads();
    {   // stage 1: merge ksub pair (two sorted 8s -> sorted top-8)
        int rowLocal = tid >> 2, t4 = tid & 3;
        const float* A = &MV[(rowLocal*4 + t4)*17];
        float* O = &MV2[rowLocal*33 + t4*8];
        int pa = 0, pb = 8;
#pragma unroll
        for (int q = 0; q < 8; q++) {
            bool ta = (pa < 8) && (pb >= 16 || A[pa] >= A[pb]);
            O[q] = ta ? A[pa] : A[pb];
            if (ta) pa++; else pb++;
        }
    }
    __syncthreads();
    if (tid < 64) {  // stage 2: 4-way merge of sorted 8-lists -> top-8
        const float* Rw = &MV2[tid*33];
        int p0 = 0, p1 = 8, p2 = 16, p3 = 24;
        size_t base = (size_t)(m0 + tid)*16 + half*8;
#pragma unroll
        for (int sel = 0; sel < 8; sel++) {
            float b0 = (p0 < 8)  ? Rw[p0] : NEG_BIG;
            float b1 = (p1 < 16) ? Rw[p1] : NEG_BIG;
            float b2 = (p2 < 24) ? Rw[p2] : NEG_BIG;
            float b3 = (p3 < 32) ? Rw[p3] : NEG_BIG;
            float mm = fmaxf(fmaxf(b0, b1), fmaxf(b2, b3));
            g_cand[base + sel] = (int)(__float_as_uint(mm) & 0xFFFu);
            if      (mm == b0) p0++;
            else if (mm == b1) p1++;
            else if (mm == b2) p2++;
            else               p3++;
        }
    }
}

// =====================================================================
// Kernel 3: exact fp32 rescore of 16 candidates/row + top-8 + softmax
// =====================================================================
__global__ __launch_bounds__(256) void rescore_kernel(float* __restrict__ out) {
    __shared__ float sd[8][16];
    int tid = threadIdx.x;
    int w = tid >> 5, lane = tid & 31;
    int row   = blockIdx.x*8 + w;
    int batch = row >> 12;
    int hl = lane & 15;

    const float* Kf = g_Kf + (size_t)batch * Nq * DKq;
    float4 qv = *(const float4*)(g_Qf + (size_t)row*DKq + hl*4);

    int c0 = g_cand[(size_t)row*16 + hl];

#pragma unroll
    for (int it = 0; it < 8; it++) {
        int j = 2*it + (lane >> 4);
        int cnd = __shfl_sync(0xFFFFFFFFu, c0, j);
        float4 kv = *(const float4*)(Kf + (size_t)cnd*DKq + hl*4);
        float p = qv.x*kv.x + qv.y*kv.y + qv.z*kv.z + qv.w*kv.w;
        p += __shfl_xor_sync(0xFFFFFFFFu, p, 1);
        p += __shfl_xor_sync(0xFFFFFFFFu, p, 2);
        p += __shfl_xor_sync(0xFFFFFFFFu, p, 4);
        p += __shfl_xor_sync(0xFFFFFFFFu, p, 8);
        if (hl == 0) sd[w][j] = p;
    }
    __syncwarp();

    float s0 = sd[w][hl];
    int   i0 = c0;

    float bv[8]; int bi[8];
#pragma unroll
    for (int sel = 0; sel < 8; sel++) {
        float v = s0; int ix = i0;
#pragma unroll
        for (int off = 16; off > 0; off >>= 1) {
            float vv = __shfl_xor_sync(0xFFFFFFFFu, v, off);
            int   ii = __shfl_xor_sync(0xFFFFFFFFu, ix, off);
            if (vv > v || (vv == v && ii < ix)) { v = vv; ix = ii; }
        }
        bv[sel] = v; bi[sel] = ix;
        if (i0 == ix) s0 = NEG_BIG;
    }

    float mx = bv[0];
    float Z = 0.f, e[8];
#pragma unroll
    for (int q = 0; q < 8; q++) { e[q] = expf(0.125f*(bv[q] - mx)); Z += e[q]; }
    float inv = 1.0f / Z;
    if (lane < 8)
        out[(size_t)row*Nq + bi[lane]] = e[lane] * inv;
}

// =====================================================================
extern "C" void kernel_launch(void* const* d_in, const int* in_sizes, int n_in,
                              void* d_out, int out_size) {
    const float* x  = (const float*)d_in[0];
    const float* Wq = (const float*)d_in[1];
    const float* Wk = (const float*)d_in[2];
    float* out = (float*)d_out;

    cudaFuncSetAttribute(edge_kernel,
                         cudaFuncAttributeMaxDynamicSharedMemorySize, SMEM_EDGE);

    proj_kernel<<<NROWS/64, 256>>>(x, Wq, Wk, out);
    edge_kernel<<<NROWS/32, 256, SMEM_EDGE>>>(out);   // 512 CTAs
    rescore_kernel<<<NROWS/8, 256>>>(out);
}